// round 1
// baseline (speedup 1.0000x reference)
#include <cuda_runtime.h>
#include <cuda_bf16.h>
#include <cstdint>
#include <cstdio>
#include <math.h>

// Problem constants
#define NTOK 2048
#define HID 2048
#define NH 32
#define NKV 8
#define HD 64
#define NE 4
#define CHUNK (NTOK / NE)   // 512
#define DQ (NH * HD)        // 2048
#define DKV (NKV * HD)      // 512

// Scratch (device globals: allocation-free rule)
__device__ float g_q[(size_t)NTOK * DQ];
__device__ float g_k[(size_t)NTOK * DKV];
__device__ float g_v[(size_t)NTOK * DKV];
__device__ float g_o[(size_t)NTOK * DQ];

// ---------------------------------------------------------------------------
// Generic tiled fp32 GEMM with optional row gather/scatter (routed experts).
// C[idx[r]] = A[idx[r]] @ W[e]   (idx==NULL -> identity rows, e = blockIdx.z)
// Tiles: BM=64, BN=64, BK=16. 128 threads, each computes 4x8.
// ---------------------------------------------------------------------------
#define BM 64
#define BN 64
#define BK 16

__global__ void __launch_bounds__(128) gemm_routed(
    const float* __restrict__ A, const float* __restrict__ W,
    float* __restrict__ C, const int* __restrict__ idx,
    int K, int Nd, int chunk)
{
    __shared__ float As[BM][BK + 1];
    __shared__ float Bs[BK][BN];
    __shared__ int rows[BM];

    const int tid = threadIdx.x;
    const float* Wp = W + (size_t)blockIdx.z * K * Nd;
    const int m0 = blockIdx.y * BM;   // row offset within chunk
    const int n0 = blockIdx.x * BN;

    if (tid < BM) {
        int lr = blockIdx.z * chunk + m0 + tid;
        rows[tid] = idx ? idx[lr] : lr;
    }
    __syncthreads();

    const int ty = tid >> 3;   // 0..15 (M groups of 4)
    const int tx = tid & 7;    // 0..7  (N groups of 8)

    float acc[4][8];
#pragma unroll
    for (int i = 0; i < 4; i++)
#pragma unroll
        for (int j = 0; j < 8; j++) acc[i][j] = 0.f;

    for (int k0 = 0; k0 < K; k0 += BK) {
        // A tile: 64x16 floats = 256 float4, 2 per thread
#pragma unroll
        for (int i = 0; i < 2; i++) {
            int f = tid + i * 128;
            int m = f >> 2;
            int kk4 = (f & 3) * 4;
            float4 v4 = *reinterpret_cast<const float4*>(
                &A[(size_t)rows[m] * K + k0 + kk4]);
            As[m][kk4 + 0] = v4.x; As[m][kk4 + 1] = v4.y;
            As[m][kk4 + 2] = v4.z; As[m][kk4 + 3] = v4.w;
        }
        // B tile: 16x64 floats = 256 float4
#pragma unroll
        for (int i = 0; i < 2; i++) {
            int f = tid + i * 128;
            int kk = f >> 4;
            int n4 = (f & 15) * 4;
            *reinterpret_cast<float4*>(&Bs[kk][n4]) =
                *reinterpret_cast<const float4*>(&Wp[(size_t)(k0 + kk) * Nd + n0 + n4]);
        }
        __syncthreads();

#pragma unroll
        for (int kk = 0; kk < BK; kk++) {
            float a[4], b[8];
#pragma unroll
            for (int i = 0; i < 4; i++) a[i] = As[ty * 4 + i][kk];
            float4 b0 = *reinterpret_cast<const float4*>(&Bs[kk][tx * 8]);
            float4 b1 = *reinterpret_cast<const float4*>(&Bs[kk][tx * 8 + 4]);
            b[0] = b0.x; b[1] = b0.y; b[2] = b0.z; b[3] = b0.w;
            b[4] = b1.x; b[5] = b1.y; b[6] = b1.z; b[7] = b1.w;
#pragma unroll
            for (int i = 0; i < 4; i++)
#pragma unroll
                for (int j = 0; j < 8; j++)
                    acc[i][j] = fmaf(a[i], b[j], acc[i][j]);
        }
        __syncthreads();
    }

#pragma unroll
    for (int i = 0; i < 4; i++) {
        size_t r = (size_t)rows[ty * 4 + i];
#pragma unroll
        for (int j = 0; j < 8; j += 4) {
            float4 v4 = make_float4(acc[i][j], acc[i][j + 1], acc[i][j + 2], acc[i][j + 3]);
            *reinterpret_cast<float4*>(&C[r * Nd + n0 + tx * 8 + j]) = v4;
        }
    }
}

// ---------------------------------------------------------------------------
// RMSNorm (per head, HD=64) + NeoX RoPE. One warp per (token, head).
// ---------------------------------------------------------------------------
__global__ void rmsnorm_rope(float* __restrict__ x, const float* __restrict__ w,
                             const int* __restrict__ pos, int n_heads)
{
    int warp = (blockIdx.x * blockDim.x + threadIdx.x) >> 5;
    int lane = threadIdx.x & 31;
    int total = NTOK * n_heads;
    if (warp >= total) return;
    int t = warp / n_heads;
    int h = warp - t * n_heads;

    float* row = x + (size_t)t * (n_heads * HD) + (size_t)h * HD;
    float x1 = row[lane];
    float x2 = row[lane + 32];
    float ss = x1 * x1 + x2 * x2;
#pragma unroll
    for (int o = 16; o; o >>= 1) ss += __shfl_xor_sync(0xffffffff, ss, o);
    float r = rsqrtf(ss * (1.0f / 64.0f) + 1e-6f);
    float y1 = x1 * r * w[lane];
    float y2 = x2 * r * w[lane + 32];

    float p = (float)pos[t];
    // inv_freq = 10000^(-lane/32); use accurate powf to match fp32 reference
    float inv = powf(10000.0f, -(float)lane * (1.0f / 32.0f));
    float f = p * inv;
    float s, c;
    sincosf(f, &s, &c);
    row[lane]      = y1 * c - y2 * s;
    row[lane + 32] = y2 * c + y1 * s;
}

// ---------------------------------------------------------------------------
// Flash attention (causal GQA). Block = (q_tile of 64, head). 64 threads,
// one query row per thread; q + accumulator in registers; 32-key KV tiles.
// ---------------------------------------------------------------------------
#define KT 32

__global__ void __launch_bounds__(64) attn_kernel(
    const float* __restrict__ q, const float* __restrict__ k,
    const float* __restrict__ v, const int* __restrict__ pos,
    float* __restrict__ o)
{
    __shared__ float ks[KT][HD];
    __shared__ float vs[KT][HD];
    __shared__ float ps[64][KT + 1];
    __shared__ int kpos[KT];

    const int h = blockIdx.y;
    const int qt = blockIdx.x;
    const int tid = threadIdx.x;
    const int qi = qt * 64 + tid;
    const int kvh = h >> 2;   // NH/NKV = 4

    float qreg[HD];
    const float* qrow = q + (size_t)qi * DQ + (size_t)h * HD;
#pragma unroll
    for (int d = 0; d < HD; d++) qreg[d] = qrow[d] * 0.125f;  // 1/sqrt(64)

    float acc[HD];
#pragma unroll
    for (int d = 0; d < HD; d++) acc[d] = 0.f;
    float m = -1e30f, l = 0.f;
    const int myp = pos[qi];

    const int ntile = 2 * qt + 2;   // keys up to (qt+1)*64 cover all unmasked
    for (int kt = 0; kt < ntile; kt++) {
        // cooperative tile load: thread tid = column d
#pragma unroll
        for (int i = 0; i < KT; i++) {
            size_t kr = (size_t)(kt * KT + i);
            ks[i][tid] = k[kr * DKV + (size_t)kvh * HD + tid];
            vs[i][tid] = v[kr * DKV + (size_t)kvh * HD + tid];
        }
        if (tid < KT) kpos[tid] = pos[kt * KT + tid];
        __syncthreads();

        float mt = -1e30f;
#pragma unroll 4
        for (int j = 0; j < KT; j++) {
            float s = 0.f;
#pragma unroll
            for (int d = 0; d < HD; d++) s = fmaf(qreg[d], ks[j][d], s);
            s = (kpos[j] <= myp) ? s : -1e30f;
            ps[tid][j] = s;
            mt = fmaxf(mt, s);
        }
        float mnew = fmaxf(m, mt);
        float alpha = __expf(m - mnew);
        l *= alpha;
#pragma unroll
        for (int d = 0; d < HD; d++) acc[d] *= alpha;
#pragma unroll 2
        for (int j = 0; j < KT; j++) {
            float p = __expf(ps[tid][j] - mnew);
            l += p;
#pragma unroll
            for (int d = 0; d < HD; d++) acc[d] = fmaf(p, vs[j][d], acc[d]);
        }
        m = mnew;
        __syncthreads();
    }

    float inv = 1.f / l;
    float* orow = o + (size_t)qi * DQ + (size_t)h * HD;
#pragma unroll
    for (int d = 0; d < HD; d++) orow[d] = acc[d] * inv;
}

// ---------------------------------------------------------------------------
extern "C" void kernel_launch(void* const* d_in, const int* in_sizes, int n_in,
                              void* d_out, int out_size)
{
    const float* hidden    = (const float*)d_in[0];
    const int*   positions = (const int*)  d_in[1];
    const int*   sort_idx  = (const int*)  d_in[2];
    const float* q_proj_w  = (const float*)d_in[3];
    const float* o_proj_w  = (const float*)d_in[4];
    const float* k_w       = (const float*)d_in[5];
    const float* v_w       = (const float*)d_in[6];
    const float* q_norm_w  = (const float*)d_in[7];
    const float* k_norm_w  = (const float*)d_in[8];
    float* out = (float*)d_out;

    float *qp, *kp, *vp, *op;
    cudaGetSymbolAddress((void**)&qp, g_q);
    cudaGetSymbolAddress((void**)&kp, g_k);
    cudaGetSymbolAddress((void**)&vp, g_v);
    cudaGetSymbolAddress((void**)&op, g_o);

    // q = routed_proj(hidden, q_proj_w, sort_idx)   [2048 x 2048]
    gemm_routed<<<dim3(DQ / BN, CHUNK / BM, NE), 128>>>(
        hidden, q_proj_w, qp, sort_idx, HID, DQ, CHUNK);
    // k = hidden @ k_w, v = hidden @ v_w            [2048 x 512]
    gemm_routed<<<dim3(DKV / BN, NTOK / BM, 1), 128>>>(
        hidden, k_w, kp, nullptr, HID, DKV, NTOK);
    gemm_routed<<<dim3(DKV / BN, NTOK / BM, 1), 128>>>(
        hidden, v_w, vp, nullptr, HID, DKV, NTOK);

    // per-head RMSNorm + RoPE
    rmsnorm_rope<<<(NTOK * NH) / 8, 256>>>(qp, q_norm_w, positions, NH);
    rmsnorm_rope<<<(NTOK * NKV) / 8, 256>>>(kp, k_norm_w, positions, NKV);

    // causal GQA flash attention
    attn_kernel<<<dim3(NTOK / 64, NH), 64>>>(qp, kp, vp, positions, op);

    // out = routed_proj(o, o_proj_w, sort_idx)
    gemm_routed<<<dim3(HID / BN, CHUNK / BM, NE), 128>>>(
        op, o_proj_w, out, sort_idx, DQ, HID, CHUNK);
}

// round 3
// speedup vs baseline: 1.8058x; 1.8058x over previous
#include <cuda_runtime.h>
#include <cuda_bf16.h>
#include <cstdint>
#include <math.h>

// Problem constants
#define NTOK 2048
#define HID 2048
#define NH 32
#define NKV 8
#define HD 64
#define NE 4
#define CHUNK (NTOK / NE)   // 512
#define DQ (NH * HD)        // 2048
#define DKV (NKV * HD)      // 512

typedef __nv_bfloat16 bf16;

// Scratch (device globals: allocation-free rule)
__device__ float g_q[(size_t)NTOK * DQ];
__device__ float g_k[(size_t)NTOK * DKV];
__device__ float g_v[(size_t)NTOK * DKV];
__device__ float g_o[(size_t)NTOK * DQ];

__device__ bf16 g_hh[(size_t)NTOK * HID];
__device__ bf16 g_hl[(size_t)NTOK * HID];
__device__ bf16 g_oh[(size_t)NTOK * DQ];
__device__ bf16 g_ol[(size_t)NTOK * DQ];

__device__ bf16 g_wq_h[(size_t)NE * HID * DQ];   // [E][DQ][HID]  (N-major, K contig)
__device__ bf16 g_wq_l[(size_t)NE * HID * DQ];
__device__ bf16 g_wo_h[(size_t)NE * DQ * HID];   // [E][HID][DQ]
__device__ bf16 g_wo_l[(size_t)NE * DQ * HID];
__device__ bf16 g_wk_h[(size_t)HID * DKV];       // [DKV][HID]
__device__ bf16 g_wk_l[(size_t)HID * DKV];
__device__ bf16 g_wv_h[(size_t)HID * DKV];
__device__ bf16 g_wv_l[(size_t)HID * DKV];

// ---------------------------------------------------------------------------
__device__ __forceinline__ uint32_t smem_u32(const void* p) {
    uint32_t a;
    asm("{ .reg .u64 t; cvta.to.shared.u64 t, %1; cvt.u32.u64 %0, t; }"
        : "=r"(a) : "l"(p));
    return a;
}

#define CP16(dst, src) \
    asm volatile("cp.async.cg.shared.global [%0], [%1], 16;" \
        :: "r"(dst), "l"(src) : "memory")
#define CP_COMMIT() asm volatile("cp.async.commit_group;" ::: "memory")

#define MMA16816(d, a, b0, b1) \
    asm volatile("mma.sync.aligned.m16n8k16.row.col.f32.bf16.bf16.f32 " \
        "{%0,%1,%2,%3}, {%4,%5,%6,%7}, {%8,%9}, {%0,%1,%2,%3};" \
        : "+f"((d)[0]), "+f"((d)[1]), "+f"((d)[2]), "+f"((d)[3]) \
        : "r"((a)[0]), "r"((a)[1]), "r"((a)[2]), "r"((a)[3]), "r"(b0), "r"(b1))

__device__ __forceinline__ void bf_split(float f, bf16& h, bf16& l) {
    h = __float2bfloat16(f);
    l = __float2bfloat16(f - __bfloat162float(h));
}

// ---------------------------------------------------------------------------
// Weight transpose + bf16 split: Wt_hi/lo[c][r] = split(W[r][c])
// ---------------------------------------------------------------------------
__global__ void transpose_split(const float* __restrict__ W,
                                bf16* __restrict__ Hi, bf16* __restrict__ Lo,
                                int R, int C) {
    __shared__ float t[32][33];
    const float* Wp = W + (size_t)blockIdx.z * R * C;
    bf16* Hp = Hi + (size_t)blockIdx.z * R * C;
    bf16* Lp = Lo + (size_t)blockIdx.z * R * C;
    int x = blockIdx.x * 32 + threadIdx.x;
    int y = blockIdx.y * 32 + threadIdx.y;
#pragma unroll
    for (int i = 0; i < 32; i += 8)
        t[threadIdx.y + i][threadIdx.x] = Wp[(size_t)(y + i) * C + x];
    __syncthreads();
    int r2 = blockIdx.y * 32 + threadIdx.x;
    int c2 = blockIdx.x * 32 + threadIdx.y;
#pragma unroll
    for (int i = 0; i < 32; i += 8) {
        float v = t[threadIdx.x][threadIdx.y + i];
        bf16 h, l;
        bf_split(v, h, l);
        Hp[(size_t)(c2 + i) * R + r2] = h;
        Lp[(size_t)(c2 + i) * R + r2] = l;
    }
}

// Elementwise split of fp32 activations into bf16 hi/lo
__global__ void split_act(const float* __restrict__ X,
                          bf16* __restrict__ Hi, bf16* __restrict__ Lo, int n4) {
    int i = blockIdx.x * blockDim.x + threadIdx.x;
    if (i >= n4) return;
    float4 v = reinterpret_cast<const float4*>(X)[i];
    bf16 h[4], l[4];
    bf_split(v.x, h[0], l[0]); bf_split(v.y, h[1], l[1]);
    bf_split(v.z, h[2], l[2]); bf_split(v.w, h[3], l[3]);
    reinterpret_cast<uint2*>(Hi)[i] = *reinterpret_cast<uint2*>(h);
    reinterpret_cast<uint2*>(Lo)[i] = *reinterpret_cast<uint2*>(l);
}

// ---------------------------------------------------------------------------
// bf16x3 mma.sync GEMM with optional row gather/scatter.
// C[rows[m]][n0+n] = sum_k A[rows[m]][k] * B[n0+n][k]   (A,B split hi/lo bf16)
// CTA tile 128x128, BK=32, 8 warps (4 M x 2 N), warp tile 32x64.
// Double-buffered smem via cp.async. Row stride 40 bf16 (conflict-free frags).
// ---------------------------------------------------------------------------
#define LDT 40
#define OPE (128 * LDT)            // elements per operand per stage
#define STAGE_E (4 * OPE)          // Ah, Al, Bh, Bl
#define GEMM_SMEM (1024 + 2 * STAGE_E * 2)

__device__ __forceinline__ void issue_tile(
    uint32_t sB, int s, int kb,
    const bf16* __restrict__ Agh, const bf16* __restrict__ Agl,
    const bf16* __restrict__ Bgh, const bf16* __restrict__ Bgl,
    const int* __restrict__ rows, int n0, int K, int tid)
{
#pragma unroll
    for (int rep = 0; rep < 2; rep++) {
        int f = tid + rep * 256;         // 0..511
        int m = f >> 2;
        int q = f & 3;
        uint32_t doff = sB + (uint32_t)s * (STAGE_E * 2) + m * (LDT * 2) + q * 16;
        size_t asrc = (size_t)rows[m] * K + kb + q * 8;
        size_t bsrc = (size_t)(n0 + m) * K + kb + q * 8;
        CP16(doff,                Agh + asrc);
        CP16(doff + OPE * 2,      Agl + asrc);
        CP16(doff + OPE * 4,      Bgh + bsrc);
        CP16(doff + OPE * 6,      Bgl + bsrc);
    }
}

__global__ void __launch_bounds__(256, 1) gemm_mma(
    const bf16* __restrict__ Agh, const bf16* __restrict__ Agl,
    const bf16* __restrict__ Bgh, const bf16* __restrict__ Bgl,
    float* __restrict__ C, const int* __restrict__ idx,
    int K, int Nd, int chunk)
{
    extern __shared__ char smc[];
    int* rows = (int*)smc;
    bf16* S = (bf16*)(smc + 1024);
    const uint32_t sB = smem_u32(S);

    const int tid = threadIdx.x;
    const int wid = tid >> 5;
    const int lane = tid & 31;
    const int m0 = blockIdx.y * 128;
    const int n0 = blockIdx.x * 128;
    const int z = blockIdx.z;
    const bf16* Bh_g = Bgh + (size_t)z * K * Nd;
    const bf16* Bl_g = Bgl + (size_t)z * K * Nd;

    if (tid < 128) {
        int lr = z * chunk + m0 + tid;
        rows[tid] = idx ? idx[lr] : lr;
    }
    __syncthreads();

    const int wm = (wid & 3) * 32;
    const int wn = (wid >> 2) * 64;

    float acc[2][8][4];
#pragma unroll
    for (int a = 0; a < 2; a++)
#pragma unroll
        for (int b = 0; b < 8; b++)
#pragma unroll
            for (int c = 0; c < 4; c++) acc[a][b][c] = 0.f;

    const int nkt = K / 32;
    issue_tile(sB, 0, 0, Agh, Agl, Bh_g, Bl_g, rows, n0, K, tid); CP_COMMIT();
    issue_tile(sB, 1, 32, Agh, Agl, Bh_g, Bl_g, rows, n0, K, tid); CP_COMMIT();

    const int rq = lane >> 2;
    const int cq = (lane & 3) * 2;

    for (int kt = 0; kt < nkt; kt++) {
        if (kt + 1 < nkt) asm volatile("cp.async.wait_group 1;" ::: "memory");
        else              asm volatile("cp.async.wait_group 0;" ::: "memory");
        __syncthreads();

        const int s = kt & 1;
        const bf16* Ah = S + (size_t)s * STAGE_E;
        const bf16* Al = Ah + OPE;
        const bf16* Bh = Ah + 2 * OPE;
        const bf16* Bl = Ah + 3 * OPE;

#pragma unroll
        for (int ks = 0; ks < 32; ks += 16) {
            uint32_t ah[2][4], al[2][4];
#pragma unroll
            for (int mi = 0; mi < 2; mi++) {
                int r = wm + mi * 16 + rq;
                ah[mi][0] = *(const uint32_t*)&Ah[r * LDT + ks + cq];
                ah[mi][1] = *(const uint32_t*)&Ah[(r + 8) * LDT + ks + cq];
                ah[mi][2] = *(const uint32_t*)&Ah[r * LDT + ks + cq + 8];
                ah[mi][3] = *(const uint32_t*)&Ah[(r + 8) * LDT + ks + cq + 8];
                al[mi][0] = *(const uint32_t*)&Al[r * LDT + ks + cq];
                al[mi][1] = *(const uint32_t*)&Al[(r + 8) * LDT + ks + cq];
                al[mi][2] = *(const uint32_t*)&Al[r * LDT + ks + cq + 8];
                al[mi][3] = *(const uint32_t*)&Al[(r + 8) * LDT + ks + cq + 8];
            }
#pragma unroll
            for (int ni = 0; ni < 8; ni++) {
                int nr = wn + ni * 8 + rq;
                uint32_t bh0 = *(const uint32_t*)&Bh[nr * LDT + ks + cq];
                uint32_t bh1 = *(const uint32_t*)&Bh[nr * LDT + ks + cq + 8];
                uint32_t bl0 = *(const uint32_t*)&Bl[nr * LDT + ks + cq];
                uint32_t bl1 = *(const uint32_t*)&Bl[nr * LDT + ks + cq + 8];
#pragma unroll
                for (int mi = 0; mi < 2; mi++) {
                    MMA16816(acc[mi][ni], ah[mi], bh0, bh1);
                    MMA16816(acc[mi][ni], ah[mi], bl0, bl1);
                    MMA16816(acc[mi][ni], al[mi], bh0, bh1);
                }
            }
        }
        __syncthreads();
        if (kt + 2 < nkt) {
            issue_tile(sB, s, (kt + 2) * 32, Agh, Agl, Bh_g, Bl_g, rows, n0, K, tid);
            CP_COMMIT();
        }
    }

    // epilogue: scatter rows
#pragma unroll
    for (int mi = 0; mi < 2; mi++) {
        int r = wm + mi * 16 + rq;
        size_t gr0 = (size_t)rows[r];
        size_t gr1 = (size_t)rows[r + 8];
#pragma unroll
        for (int ni = 0; ni < 8; ni++) {
            int col = n0 + wn + ni * 8 + cq;
            *reinterpret_cast<float2*>(&C[gr0 * Nd + col]) =
                make_float2(acc[mi][ni][0], acc[mi][ni][1]);
            *reinterpret_cast<float2*>(&C[gr1 * Nd + col]) =
                make_float2(acc[mi][ni][2], acc[mi][ni][3]);
        }
    }
}

// ---------------------------------------------------------------------------
// RMSNorm (per head, HD=64) + NeoX RoPE. One warp per (token, head).
// ---------------------------------------------------------------------------
__global__ void rmsnorm_rope(float* __restrict__ x, const float* __restrict__ w,
                             const int* __restrict__ pos, int n_heads)
{
    int warp = (blockIdx.x * blockDim.x + threadIdx.x) >> 5;
    int lane = threadIdx.x & 31;
    int total = NTOK * n_heads;
    if (warp >= total) return;
    int t = warp / n_heads;
    int h = warp - t * n_heads;

    float* row = x + (size_t)t * (n_heads * HD) + (size_t)h * HD;
    float x1 = row[lane];
    float x2 = row[lane + 32];
    float ss = x1 * x1 + x2 * x2;
#pragma unroll
    for (int o = 16; o; o >>= 1) ss += __shfl_xor_sync(0xffffffff, ss, o);
    float r = rsqrtf(ss * (1.0f / 64.0f) + 1e-6f);
    float y1 = x1 * r * w[lane];
    float y2 = x2 * r * w[lane + 32];

    float p = (float)pos[t];
    float inv = powf(10000.0f, -(float)lane * (1.0f / 32.0f));
    float f = p * inv;
    float s, c;
    sincosf(f, &s, &c);
    row[lane]      = y1 * c - y2 * s;
    row[lane + 32] = y2 * c + y1 * s;
}

// ---------------------------------------------------------------------------
// Flash attention (causal GQA). Block = (q_tile of 64, head). 64 threads,
// one query row per thread; q + accumulator in registers; 32-key KV tiles.
// ---------------------------------------------------------------------------
#define KT 32

__global__ void __launch_bounds__(64) attn_kernel(
    const float* __restrict__ q, const float* __restrict__ k,
    const float* __restrict__ v, const int* __restrict__ pos,
    float* __restrict__ o)
{
    __shared__ float ks[KT][HD];
    __shared__ float vs[KT][HD];
    __shared__ float ps[64][KT + 1];
    __shared__ int kpos[KT];

    const int h = blockIdx.y;
    const int qt = blockIdx.x;
    const int tid = threadIdx.x;
    const int qi = qt * 64 + tid;
    const int kvh = h >> 2;

    float qreg[HD];
    const float* qrow = q + (size_t)qi * DQ + (size_t)h * HD;
#pragma unroll
    for (int d = 0; d < HD; d++) qreg[d] = qrow[d] * 0.125f;

    float acc[HD];
#pragma unroll
    for (int d = 0; d < HD; d++) acc[d] = 0.f;
    float m = -1e30f, l = 0.f;
    const int myp = pos[qi];

    const int ntile = 2 * qt + 2;
    for (int kt = 0; kt < ntile; kt++) {
#pragma unroll
        for (int i = 0; i < KT; i++) {
            size_t kr = (size_t)(kt * KT + i);
            ks[i][tid] = k[kr * DKV + (size_t)kvh * HD + tid];
            vs[i][tid] = v[kr * DKV + (size_t)kvh * HD + tid];
        }
        if (tid < KT) kpos[tid] = pos[kt * KT + tid];
        __syncthreads();

        float mt = -1e30f;
#pragma unroll 4
        for (int j = 0; j < KT; j++) {
            float s = 0.f;
#pragma unroll
            for (int d = 0; d < HD; d++) s = fmaf(qreg[d], ks[j][d], s);
            s = (kpos[j] <= myp) ? s : -1e30f;
            ps[tid][j] = s;
            mt = fmaxf(mt, s);
        }
        float mnew = fmaxf(m, mt);
        float alpha = __expf(m - mnew);
        l *= alpha;
#pragma unroll
        for (int d = 0; d < HD; d++) acc[d] *= alpha;
#pragma unroll 2
        for (int j = 0; j < KT; j++) {
            float p = __expf(ps[tid][j] - mnew);
            l += p;
#pragma unroll
            for (int d = 0; d < HD; d++) acc[d] = fmaf(p, vs[j][d], acc[d]);
        }
        m = mnew;
        __syncthreads();
    }

    float inv = 1.f / l;
    float* orow = o + (size_t)qi * DQ + (size_t)h * HD;
#pragma unroll
    for (int d = 0; d < HD; d++) orow[d] = acc[d] * inv;
}

// ---------------------------------------------------------------------------
extern "C" void kernel_launch(void* const* d_in, const int* in_sizes, int n_in,
                              void* d_out, int out_size)
{
    const float* hidden    = (const float*)d_in[0];
    const int*   positions = (const int*)  d_in[1];
    const int*   sort_idx  = (const int*)  d_in[2];
    const float* q_proj_w  = (const float*)d_in[3];
    const float* o_proj_w  = (const float*)d_in[4];
    const float* k_w       = (const float*)d_in[5];
    const float* v_w       = (const float*)d_in[6];
    const float* q_norm_w  = (const float*)d_in[7];
    const float* k_norm_w  = (const float*)d_in[8];
    float* out = (float*)d_out;

    float *qp, *kp, *vp, *op;
    bf16 *hh, *hl, *oh, *ol, *wqh, *wql, *woh, *wol, *wkh, *wkl, *wvh, *wvl;
    cudaGetSymbolAddress((void**)&qp, g_q);
    cudaGetSymbolAddress((void**)&kp, g_k);
    cudaGetSymbolAddress((void**)&vp, g_v);
    cudaGetSymbolAddress((void**)&op, g_o);
    cudaGetSymbolAddress((void**)&hh, g_hh);
    cudaGetSymbolAddress((void**)&hl, g_hl);
    cudaGetSymbolAddress((void**)&oh, g_oh);
    cudaGetSymbolAddress((void**)&ol, g_ol);
    cudaGetSymbolAddress((void**)&wqh, g_wq_h);
    cudaGetSymbolAddress((void**)&wql, g_wq_l);
    cudaGetSymbolAddress((void**)&woh, g_wo_h);
    cudaGetSymbolAddress((void**)&wol, g_wo_l);
    cudaGetSymbolAddress((void**)&wkh, g_wk_h);
    cudaGetSymbolAddress((void**)&wkl, g_wk_l);
    cudaGetSymbolAddress((void**)&wvh, g_wv_h);
    cudaGetSymbolAddress((void**)&wvl, g_wv_l);

    cudaFuncSetAttribute(gemm_mma, cudaFuncAttributeMaxDynamicSharedMemorySize, GEMM_SMEM);

    // weight transposes + bf16 hi/lo split  ([N][K] layout)
    transpose_split<<<dim3(DQ / 32, HID / 32, NE), dim3(32, 8)>>>(q_proj_w, wqh, wql, HID, DQ);
    transpose_split<<<dim3(HID / 32, DQ / 32, NE), dim3(32, 8)>>>(o_proj_w, woh, wol, DQ, HID);
    transpose_split<<<dim3(DKV / 32, HID / 32, 1), dim3(32, 8)>>>(k_w, wkh, wkl, HID, DKV);
    transpose_split<<<dim3(DKV / 32, HID / 32, 1), dim3(32, 8)>>>(v_w, wvh, wvl, HID, DKV);

    // activation split
    split_act<<<(NTOK * HID / 4 + 255) / 256, 256>>>(hidden, hh, hl, NTOK * HID / 4);

    // q = routed_proj(hidden, q_proj_w, sort_idx)
    gemm_mma<<<dim3(DQ / 128, CHUNK / 128, NE), 256, GEMM_SMEM>>>(
        hh, hl, wqh, wql, qp, sort_idx, HID, DQ, CHUNK);
    // k, v projections
    gemm_mma<<<dim3(DKV / 128, NTOK / 128, 1), 256, GEMM_SMEM>>>(
        hh, hl, wkh, wkl, kp, nullptr, HID, DKV, NTOK);
    gemm_mma<<<dim3(DKV / 128, NTOK / 128, 1), 256, GEMM_SMEM>>>(
        hh, hl, wvh, wvl, vp, nullptr, HID, DKV, NTOK);

    // per-head RMSNorm + RoPE
    rmsnorm_rope<<<(NTOK * NH) / 8, 256>>>(qp, q_norm_w, positions, NH);
    rmsnorm_rope<<<(NTOK * NKV) / 8, 256>>>(kp, k_norm_w, positions, NKV);

    // causal GQA flash attention
    attn_kernel<<<dim3(NTOK / 64, NH), 64>>>(qp, kp, vp, positions, op);

    // split attention output, then out = routed_proj(o, o_proj_w, sort_idx)
    split_act<<<(NTOK * DQ / 4 + 255) / 256, 256>>>(op, oh, ol, NTOK * DQ / 4);
    gemm_mma<<<dim3(HID / 128, CHUNK / 128, NE), 256, GEMM_SMEM>>>(
        oh, ol, woh, wol, out, sort_idx, DQ, HID, CHUNK);
}

// round 4
// speedup vs baseline: 3.3747x; 1.8688x over previous
#include <cuda_runtime.h>
#include <cuda_bf16.h>
#include <cstdint>
#include <math.h>

// Problem constants
#define NTOK 2048
#define HID 2048
#define NH 32
#define NKV 8
#define HD 64
#define NE 4
#define CHUNK (NTOK / NE)   // 512
#define DQ (NH * HD)        // 2048
#define DKV (NKV * HD)      // 512

typedef __nv_bfloat16 bf16;

// Scratch (device globals: allocation-free rule)
__device__ float g_q[(size_t)NTOK * DQ];
__device__ float g_k[(size_t)NTOK * DKV];
__device__ float g_v[(size_t)NTOK * DKV];

__device__ bf16 g_hh[(size_t)NTOK * HID];
__device__ bf16 g_hl[(size_t)NTOK * HID];
__device__ bf16 g_oh[(size_t)NTOK * DQ];    // attn output hi
__device__ bf16 g_ol[(size_t)NTOK * DQ];    // attn output lo

__device__ bf16 g_qh[(size_t)NTOK * DQ];    // roped q hi (pre-scaled 1/8)
__device__ bf16 g_ql[(size_t)NTOK * DQ];
__device__ bf16 g_kh2[(size_t)NTOK * DKV];  // roped k hi
__device__ bf16 g_kl2[(size_t)NTOK * DKV];
__device__ bf16 g_vh[(size_t)NTOK * DKV];
__device__ bf16 g_vl[(size_t)NTOK * DKV];

__device__ bf16 g_wq_h[(size_t)NE * HID * DQ];   // [E][DQ][HID]
__device__ bf16 g_wq_l[(size_t)NE * HID * DQ];
__device__ bf16 g_wo_h[(size_t)NE * DQ * HID];   // [E][HID][DQ]
__device__ bf16 g_wo_l[(size_t)NE * DQ * HID];
__device__ bf16 g_wk_h[(size_t)HID * DKV];       // [DKV][HID]
__device__ bf16 g_wk_l[(size_t)HID * DKV];
__device__ bf16 g_wv_h[(size_t)HID * DKV];
__device__ bf16 g_wv_l[(size_t)HID * DKV];

// ---------------------------------------------------------------------------
__device__ __forceinline__ uint32_t smem_u32(const void* p) {
    uint32_t a;
    asm("{ .reg .u64 t; cvta.to.shared.u64 t, %1; cvt.u32.u64 %0, t; }"
        : "=r"(a) : "l"(p));
    return a;
}

#define CP16(dst, src) \
    asm volatile("cp.async.cg.shared.global [%0], [%1], 16;" \
        :: "r"(dst), "l"(src) : "memory")
#define CP_COMMIT() asm volatile("cp.async.commit_group;" ::: "memory")

#define MMA16816(d, a, b0, b1) \
    asm volatile("mma.sync.aligned.m16n8k16.row.col.f32.bf16.bf16.f32 " \
        "{%0,%1,%2,%3}, {%4,%5,%6,%7}, {%8,%9}, {%0,%1,%2,%3};" \
        : "+f"((d)[0]), "+f"((d)[1]), "+f"((d)[2]), "+f"((d)[3]) \
        : "r"((a)[0]), "r"((a)[1]), "r"((a)[2]), "r"((a)[3]), "r"(b0), "r"(b1))

#define LDSM_T4(r0, r1, r2, r3, a) \
    asm volatile("ldmatrix.sync.aligned.m8n8.x4.trans.shared.b16 {%0,%1,%2,%3}, [%4];" \
        : "=r"(r0), "=r"(r1), "=r"(r2), "=r"(r3) : "r"(a))

__device__ __forceinline__ void bf_split(float f, bf16& h, bf16& l) {
    h = __float2bfloat16(f);
    l = __float2bfloat16(f - __bfloat162float(h));
}

// split (a,b) into packed bf16x2 hi and lo words (a = low half)
__device__ __forceinline__ void splitpack2(float a, float b, uint32_t& hi, uint32_t& lo) {
    bf16 ha, la, hb, lb;
    bf_split(a, ha, la);
    bf_split(b, hb, lb);
    hi = ((uint32_t)__bfloat16_as_ushort(hb) << 16) | __bfloat16_as_ushort(ha);
    lo = ((uint32_t)__bfloat16_as_ushort(lb) << 16) | __bfloat16_as_ushort(la);
}

// ---------------------------------------------------------------------------
// Weight transpose + bf16 split: Wt_hi/lo[c][r] = split(W[r][c])
// ---------------------------------------------------------------------------
__global__ void transpose_split(const float* __restrict__ W,
                                bf16* __restrict__ Hi, bf16* __restrict__ Lo,
                                int R, int C) {
    __shared__ float t[32][33];
    const float* Wp = W + (size_t)blockIdx.z * R * C;
    bf16* Hp = Hi + (size_t)blockIdx.z * R * C;
    bf16* Lp = Lo + (size_t)blockIdx.z * R * C;
    int x = blockIdx.x * 32 + threadIdx.x;
    int y = blockIdx.y * 32 + threadIdx.y;
#pragma unroll
    for (int i = 0; i < 32; i += 8)
        t[threadIdx.y + i][threadIdx.x] = Wp[(size_t)(y + i) * C + x];
    __syncthreads();
    int r2 = blockIdx.y * 32 + threadIdx.x;
    int c2 = blockIdx.x * 32 + threadIdx.y;
#pragma unroll
    for (int i = 0; i < 32; i += 8) {
        float v = t[threadIdx.x][threadIdx.y + i];
        bf16 h, l;
        bf_split(v, h, l);
        Hp[(size_t)(c2 + i) * R + r2] = h;
        Lp[(size_t)(c2 + i) * R + r2] = l;
    }
}

// Elementwise split of fp32 activations into bf16 hi/lo
__global__ void split_act(const float* __restrict__ X,
                          bf16* __restrict__ Hi, bf16* __restrict__ Lo, int n4) {
    int i = blockIdx.x * blockDim.x + threadIdx.x;
    if (i >= n4) return;
    float4 v = reinterpret_cast<const float4*>(X)[i];
    bf16 h[4], l[4];
    bf_split(v.x, h[0], l[0]); bf_split(v.y, h[1], l[1]);
    bf_split(v.z, h[2], l[2]); bf_split(v.w, h[3], l[3]);
    reinterpret_cast<uint2*>(Hi)[i] = *reinterpret_cast<uint2*>(h);
    reinterpret_cast<uint2*>(Lo)[i] = *reinterpret_cast<uint2*>(l);
}

// ---------------------------------------------------------------------------
// bf16x3 mma.sync GEMM with optional row gather/scatter.
// ---------------------------------------------------------------------------
#define LDT 40
#define OPE (128 * LDT)
#define STAGE_E (4 * OPE)
#define GEMM_SMEM (1024 + 2 * STAGE_E * 2)

__device__ __forceinline__ void issue_tile(
    uint32_t sB, int s, int kb,
    const bf16* __restrict__ Agh, const bf16* __restrict__ Agl,
    const bf16* __restrict__ Bgh, const bf16* __restrict__ Bgl,
    const int* __restrict__ rows, int n0, int K, int tid)
{
#pragma unroll
    for (int rep = 0; rep < 2; rep++) {
        int f = tid + rep * 256;
        int m = f >> 2;
        int q = f & 3;
        uint32_t doff = sB + (uint32_t)s * (STAGE_E * 2) + m * (LDT * 2) + q * 16;
        size_t asrc = (size_t)rows[m] * K + kb + q * 8;
        size_t bsrc = (size_t)(n0 + m) * K + kb + q * 8;
        CP16(doff,                Agh + asrc);
        CP16(doff + OPE * 2,      Agl + asrc);
        CP16(doff + OPE * 4,      Bgh + bsrc);
        CP16(doff + OPE * 6,      Bgl + bsrc);
    }
}

__global__ void __launch_bounds__(256, 1) gemm_mma(
    const bf16* __restrict__ Agh, const bf16* __restrict__ Agl,
    const bf16* __restrict__ Bgh, const bf16* __restrict__ Bgl,
    float* __restrict__ C, const int* __restrict__ idx,
    int K, int Nd, int chunk)
{
    extern __shared__ char smc[];
    int* rows = (int*)smc;
    bf16* S = (bf16*)(smc + 1024);
    const uint32_t sB = smem_u32(S);

    const int tid = threadIdx.x;
    const int wid = tid >> 5;
    const int lane = tid & 31;
    const int m0 = blockIdx.y * 128;
    const int n0 = blockIdx.x * 128;
    const int z = blockIdx.z;
    const bf16* Bh_g = Bgh + (size_t)z * K * Nd;
    const bf16* Bl_g = Bgl + (size_t)z * K * Nd;

    if (tid < 128) {
        int lr = z * chunk + m0 + tid;
        rows[tid] = idx ? idx[lr] : lr;
    }
    __syncthreads();

    const int wm = (wid & 3) * 32;
    const int wn = (wid >> 2) * 64;

    float acc[2][8][4];
#pragma unroll
    for (int a = 0; a < 2; a++)
#pragma unroll
        for (int b = 0; b < 8; b++)
#pragma unroll
            for (int c = 0; c < 4; c++) acc[a][b][c] = 0.f;

    const int nkt = K / 32;
    issue_tile(sB, 0, 0, Agh, Agl, Bh_g, Bl_g, rows, n0, K, tid); CP_COMMIT();
    issue_tile(sB, 1, 32, Agh, Agl, Bh_g, Bl_g, rows, n0, K, tid); CP_COMMIT();

    const int rq = lane >> 2;
    const int cq = (lane & 3) * 2;

    for (int kt = 0; kt < nkt; kt++) {
        if (kt + 1 < nkt) asm volatile("cp.async.wait_group 1;" ::: "memory");
        else              asm volatile("cp.async.wait_group 0;" ::: "memory");
        __syncthreads();

        const int s = kt & 1;
        const bf16* Ah = S + (size_t)s * STAGE_E;
        const bf16* Al = Ah + OPE;
        const bf16* Bh = Ah + 2 * OPE;
        const bf16* Bl = Ah + 3 * OPE;

#pragma unroll
        for (int ks = 0; ks < 32; ks += 16) {
            uint32_t ah[2][4], al[2][4];
#pragma unroll
            for (int mi = 0; mi < 2; mi++) {
                int r = wm + mi * 16 + rq;
                ah[mi][0] = *(const uint32_t*)&Ah[r * LDT + ks + cq];
                ah[mi][1] = *(const uint32_t*)&Ah[(r + 8) * LDT + ks + cq];
                ah[mi][2] = *(const uint32_t*)&Ah[r * LDT + ks + cq + 8];
                ah[mi][3] = *(const uint32_t*)&Ah[(r + 8) * LDT + ks + cq + 8];
                al[mi][0] = *(const uint32_t*)&Al[r * LDT + ks + cq];
                al[mi][1] = *(const uint32_t*)&Al[(r + 8) * LDT + ks + cq];
                al[mi][2] = *(const uint32_t*)&Al[r * LDT + ks + cq + 8];
                al[mi][3] = *(const uint32_t*)&Al[(r + 8) * LDT + ks + cq + 8];
            }
#pragma unroll
            for (int ni = 0; ni < 8; ni++) {
                int nr = wn + ni * 8 + rq;
                uint32_t bh0 = *(const uint32_t*)&Bh[nr * LDT + ks + cq];
                uint32_t bh1 = *(const uint32_t*)&Bh[nr * LDT + ks + cq + 8];
                uint32_t bl0 = *(const uint32_t*)&Bl[nr * LDT + ks + cq];
                uint32_t bl1 = *(const uint32_t*)&Bl[nr * LDT + ks + cq + 8];
#pragma unroll
                for (int mi = 0; mi < 2; mi++) {
                    MMA16816(acc[mi][ni], ah[mi], bh0, bh1);
                    MMA16816(acc[mi][ni], ah[mi], bl0, bl1);
                    MMA16816(acc[mi][ni], al[mi], bh0, bh1);
                }
            }
        }
        __syncthreads();
        if (kt + 2 < nkt) {
            issue_tile(sB, s, (kt + 2) * 32, Agh, Agl, Bh_g, Bl_g, rows, n0, K, tid);
            CP_COMMIT();
        }
    }

#pragma unroll
    for (int mi = 0; mi < 2; mi++) {
        int r = wm + mi * 16 + rq;
        size_t gr0 = (size_t)rows[r];
        size_t gr1 = (size_t)rows[r + 8];
#pragma unroll
        for (int ni = 0; ni < 8; ni++) {
            int col = n0 + wn + ni * 8 + cq;
            *reinterpret_cast<float2*>(&C[gr0 * Nd + col]) =
                make_float2(acc[mi][ni][0], acc[mi][ni][1]);
            *reinterpret_cast<float2*>(&C[gr1 * Nd + col]) =
                make_float2(acc[mi][ni][2], acc[mi][ni][3]);
        }
    }
}

// ---------------------------------------------------------------------------
// RMSNorm + NeoX RoPE, writing bf16 hi/lo splits (scaled by sc).
// ---------------------------------------------------------------------------
__global__ void rmsnorm_rope_split(const float* __restrict__ x,
                                   const float* __restrict__ w,
                                   const int* __restrict__ pos, int n_heads,
                                   float sc, bf16* __restrict__ Hi,
                                   bf16* __restrict__ Lo)
{
    int warp = (blockIdx.x * blockDim.x + threadIdx.x) >> 5;
    int lane = threadIdx.x & 31;
    int total = NTOK * n_heads;
    if (warp >= total) return;
    int t = warp / n_heads;
    int h = warp - t * n_heads;

    const float* row = x + (size_t)t * (n_heads * HD) + (size_t)h * HD;
    float x1 = row[lane];
    float x2 = row[lane + 32];
    float ss = x1 * x1 + x2 * x2;
#pragma unroll
    for (int o = 16; o; o >>= 1) ss += __shfl_xor_sync(0xffffffff, ss, o);
    float r = rsqrtf(ss * (1.0f / 64.0f) + 1e-6f);
    float y1 = x1 * r * w[lane];
    float y2 = x2 * r * w[lane + 32];

    float p = (float)pos[t];
    float inv = powf(10000.0f, -(float)lane * (1.0f / 32.0f));
    float f = p * inv;
    float s, c;
    sincosf(f, &s, &c);
    float o1 = (y1 * c - y2 * s) * sc;
    float o2 = (y2 * c + y1 * s) * sc;

    size_t base = (size_t)t * (n_heads * HD) + (size_t)h * HD;
    bf16 h1, l1, h2, l2;
    bf_split(o1, h1, l1);
    bf_split(o2, h2, l2);
    Hi[base + lane] = h1;      Lo[base + lane] = l1;
    Hi[base + lane + 32] = h2; Lo[base + lane + 32] = l2;
}

// ---------------------------------------------------------------------------
// Tensor-core flash attention (causal GQA), bf16x3.
// Block = (128 q rows, head). 8 warps x 16 rows. KV tiles of 64 keys,
// double-buffered cp.async. K B-frags via LDS.32; V via ldmatrix.x4.trans.
// Outputs bf16 hi/lo splits directly (o_proj input).
// ---------------------------------------------------------------------------
#define AQ 128
#define AK 64
#define LDK 72
#define QSM (AQ * LDK)     // 9216 elements
#define KSM (AK * LDK)     // 4608 elements
#define ASMEM ((2 * QSM + 8 * KSM) * 2 + 2 * AK * 4)

__device__ __forceinline__ void attn_issue(
    uint32_t sbase, int s, int kt, int kvh, int tid,
    const bf16* __restrict__ kh_g, const bf16* __restrict__ kl_g,
    const bf16* __restrict__ vh_g, const bf16* __restrict__ vl_g,
    const int* __restrict__ pos, int* __restrict__ kpos_sm)
{
#pragma unroll
    for (int i = 0; i < 8; i++) {
        int f = tid + i * 256;          // 0..2047
        int arr = f >> 9;
        int r = (f >> 3) & 63;
        int seg = f & 7;
        const bf16* src = (arr == 0) ? kh_g : (arr == 1) ? kl_g
                        : (arr == 2) ? vh_g : vl_g;
        uint32_t dst = sbase + (uint32_t)(2 * QSM + (s * 4 + arr) * KSM + r * LDK) * 2
                     + seg * 16;
        CP16(dst, src + (size_t)(kt * AK + r) * DKV + (size_t)kvh * HD + seg * 8);
    }
    if (tid < AK) kpos_sm[s * AK + tid] = pos[kt * AK + tid];
    CP_COMMIT();
}

__global__ void __launch_bounds__(256, 1) attn_mma(
    const bf16* __restrict__ qh_g, const bf16* __restrict__ ql_g,
    const bf16* __restrict__ kh_g, const bf16* __restrict__ kl_g,
    const bf16* __restrict__ vh_g, const bf16* __restrict__ vl_g,
    const int* __restrict__ pos,
    bf16* __restrict__ oh_g, bf16* __restrict__ ol_g)
{
    extern __shared__ char sm[];
    const uint32_t sbase = smem_u32(sm);
    int* kpos = (int*)(sm + (size_t)(2 * QSM + 8 * KSM) * 2);

    const int tid = threadIdx.x;
    const int w = tid >> 5;
    const int l = tid & 31;
    const int qt = blockIdx.x;
    const int h = blockIdx.y;
    const int kvh = h >> 2;
    const int q0 = qt * AQ;
    const int ntile = 2 * qt + 2;

    // prefetch KV tiles 0,1
    attn_issue(sbase, 0, 0, kvh, tid, kh_g, kl_g, vh_g, vl_g, pos, kpos);
    attn_issue(sbase, 1, 1, kvh, tid, kh_g, kl_g, vh_g, vl_g, pos, kpos);

    // stage Q (hi, lo) into smem with padded rows
#pragma unroll
    for (int i = 0; i < 4; i++) {
        int f = tid + i * 256;          // 0..1023
        int r = f >> 3;
        int seg = f & 7;
        uint4 v1 = *reinterpret_cast<const uint4*>(
            qh_g + (size_t)(q0 + r) * DQ + (size_t)h * HD + seg * 8);
        *reinterpret_cast<uint4*>(sm + (size_t)(r * LDK) * 2 + seg * 16) = v1;
        uint4 v2 = *reinterpret_cast<const uint4*>(
            ql_g + (size_t)(q0 + r) * DQ + (size_t)h * HD + seg * 8);
        *reinterpret_cast<uint4*>(sm + (size_t)(QSM + r * LDK) * 2 + seg * 16) = v2;
    }
    __syncthreads();

    const int rq = l >> 2;
    const int cq = l & 3;            // word index
    const int row0 = w * 16 + rq;

    // Q fragments (A operand), kept in registers
    const uint32_t* smw = (const uint32_t*)sm;
    uint32_t qfh[4][4], qfl[4][4];
#pragma unroll
    for (int kf = 0; kf < 4; kf++) {
        int b = kf * 8 + cq;
        qfh[kf][0] = smw[row0 * 36 + b];
        qfh[kf][1] = smw[(row0 + 8) * 36 + b];
        qfh[kf][2] = smw[row0 * 36 + b + 4];
        qfh[kf][3] = smw[(row0 + 8) * 36 + b + 4];
        qfl[kf][0] = smw[(QSM / 2) + row0 * 36 + b];
        qfl[kf][1] = smw[(QSM / 2) + (row0 + 8) * 36 + b];
        qfl[kf][2] = smw[(QSM / 2) + row0 * 36 + b + 4];
        qfl[kf][3] = smw[(QSM / 2) + (row0 + 8) * 36 + b + 4];
    }
    const int qp0 = pos[q0 + row0];
    const int qp1 = pos[q0 + row0 + 8];

    float o[8][4];
#pragma unroll
    for (int nf = 0; nf < 8; nf++)
#pragma unroll
        for (int e = 0; e < 4; e++) o[nf][e] = 0.f;
    float m0 = -1e30f, m1 = -1e30f, l0 = 0.f, l1 = 0.f;

    const int lrow16 = l & 15;
    const int lsel = l >> 4;

    for (int kt = 0; kt < ntile; kt++) {
        if (kt + 1 < ntile) asm volatile("cp.async.wait_group 1;" ::: "memory");
        else                asm volatile("cp.async.wait_group 0;" ::: "memory");
        __syncthreads();

        const int s = kt & 1;
        const uint32_t* kwh = smw + (2 * QSM + (s * 4 + 0) * KSM) / 2;
        const uint32_t* kwl = smw + (2 * QSM + (s * 4 + 1) * KSM) / 2;
        const uint32_t vhb = sbase + (uint32_t)(2 * QSM + (s * 4 + 2) * KSM) * 2;
        const uint32_t vlb = sbase + (uint32_t)(2 * QSM + (s * 4 + 3) * KSM) * 2;

        // S = Q K^T (3 terms)
        float sv[8][4];
#pragma unroll
        for (int nf = 0; nf < 8; nf++)
#pragma unroll
            for (int e = 0; e < 4; e++) sv[nf][e] = 0.f;

#pragma unroll
        for (int nf = 0; nf < 8; nf++) {
            int kbase = (nf * 8 + rq) * 36 + cq;
#pragma unroll
            for (int kf = 0; kf < 4; kf++) {
                uint32_t bh0 = kwh[kbase + kf * 8];
                uint32_t bh1 = kwh[kbase + kf * 8 + 4];
                uint32_t bl0 = kwl[kbase + kf * 8];
                uint32_t bl1 = kwl[kbase + kf * 8 + 4];
                MMA16816(sv[nf], qfh[kf], bh0, bh1);
                MMA16816(sv[nf], qfh[kf], bl0, bl1);
                MMA16816(sv[nf], qfl[kf], bh0, bh1);
            }
        }

        // causal mask (only the last two tiles can cross the diagonal)
        if (kt >= 2 * qt) {
            const int* kp = kpos + s * AK;
#pragma unroll
            for (int nf = 0; nf < 8; nf++) {
                int c = nf * 8 + cq * 2;
                int k0 = kp[c], k1 = kp[c + 1];
                if (k0 > qp0) sv[nf][0] = -1e30f;
                if (k1 > qp0) sv[nf][1] = -1e30f;
                if (k0 > qp1) sv[nf][2] = -1e30f;
                if (k1 > qp1) sv[nf][3] = -1e30f;
            }
        }

        // online softmax
        float mt0 = -1e30f, mt1 = -1e30f;
#pragma unroll
        for (int nf = 0; nf < 8; nf++) {
            mt0 = fmaxf(mt0, fmaxf(sv[nf][0], sv[nf][1]));
            mt1 = fmaxf(mt1, fmaxf(sv[nf][2], sv[nf][3]));
        }
        mt0 = fmaxf(mt0, __shfl_xor_sync(0xffffffff, mt0, 1));
        mt0 = fmaxf(mt0, __shfl_xor_sync(0xffffffff, mt0, 2));
        mt1 = fmaxf(mt1, __shfl_xor_sync(0xffffffff, mt1, 1));
        mt1 = fmaxf(mt1, __shfl_xor_sync(0xffffffff, mt1, 2));
        float mn0 = fmaxf(m0, mt0), mn1 = fmaxf(m1, mt1);
        float a0 = __expf(m0 - mn0), a1 = __expf(m1 - mn1);
        m0 = mn0; m1 = mn1;
#pragma unroll
        for (int nf = 0; nf < 8; nf++) {
            o[nf][0] *= a0; o[nf][1] *= a0;
            o[nf][2] *= a1; o[nf][3] *= a1;
        }
        float rs0 = 0.f, rs1 = 0.f;
#pragma unroll
        for (int nf = 0; nf < 8; nf++) {
            sv[nf][0] = __expf(sv[nf][0] - mn0); rs0 += sv[nf][0];
            sv[nf][1] = __expf(sv[nf][1] - mn0); rs0 += sv[nf][1];
            sv[nf][2] = __expf(sv[nf][2] - mn1); rs1 += sv[nf][2];
            sv[nf][3] = __expf(sv[nf][3] - mn1); rs1 += sv[nf][3];
        }
        rs0 += __shfl_xor_sync(0xffffffff, rs0, 1);
        rs0 += __shfl_xor_sync(0xffffffff, rs0, 2);
        rs1 += __shfl_xor_sync(0xffffffff, rs1, 1);
        rs1 += __shfl_xor_sync(0xffffffff, rs1, 2);
        l0 = l0 * a0 + rs0;
        l1 = l1 * a1 + rs1;

        // O += P V (3 terms), per key k-fragment
#pragma unroll
        for (int kfk = 0; kfk < 4; kfk++) {
            uint32_t pah[4], pal[4];
            splitpack2(sv[2 * kfk][0], sv[2 * kfk][1], pah[0], pal[0]);
            splitpack2(sv[2 * kfk][2], sv[2 * kfk][3], pah[1], pal[1]);
            splitpack2(sv[2 * kfk + 1][0], sv[2 * kfk + 1][1], pah[2], pal[2]);
            splitpack2(sv[2 * kfk + 1][2], sv[2 * kfk + 1][3], pah[3], pal[3]);

            uint32_t vfh[8][2], vfl[8][2];
#pragma unroll
            for (int nfp = 0; nfp < 4; nfp++) {
                uint32_t off = (uint32_t)((kfk * 16 + lrow16) * LDK
                                          + nfp * 16 + lsel * 8) * 2;
                uint32_t r0, r1, r2, r3;
                LDSM_T4(r0, r1, r2, r3, vhb + off);
                vfh[2 * nfp][0] = r0;     vfh[2 * nfp][1] = r1;
                vfh[2 * nfp + 1][0] = r2; vfh[2 * nfp + 1][1] = r3;
                LDSM_T4(r0, r1, r2, r3, vlb + off);
                vfl[2 * nfp][0] = r0;     vfl[2 * nfp][1] = r1;
                vfl[2 * nfp + 1][0] = r2; vfl[2 * nfp + 1][1] = r3;
            }
#pragma unroll
            for (int nf = 0; nf < 8; nf++) {
                MMA16816(o[nf], pah, vfh[nf][0], vfh[nf][1]);
                MMA16816(o[nf], pah, vfl[nf][0], vfl[nf][1]);
                MMA16816(o[nf], pal, vfh[nf][0], vfh[nf][1]);
            }
        }

        __syncthreads();
        if (kt + 2 < ntile)
            attn_issue(sbase, s, kt + 2, kvh, tid, kh_g, kl_g, vh_g, vl_g, pos, kpos);
    }

    // write O (pre-split bf16 hi/lo for o_proj)
    float i0 = 1.f / l0, i1 = 1.f / l1;
    int g0 = q0 + w * 16 + rq;
    int g1 = g0 + 8;
#pragma unroll
    for (int nf = 0; nf < 8; nf++) {
        int col = h * HD + nf * 8 + cq * 2;
        uint32_t ph, pl;
        splitpack2(o[nf][0] * i0, o[nf][1] * i0, ph, pl);
        *reinterpret_cast<uint32_t*>(oh_g + (size_t)g0 * DQ + col) = ph;
        *reinterpret_cast<uint32_t*>(ol_g + (size_t)g0 * DQ + col) = pl;
        splitpack2(o[nf][2] * i1, o[nf][3] * i1, ph, pl);
        *reinterpret_cast<uint32_t*>(oh_g + (size_t)g1 * DQ + col) = ph;
        *reinterpret_cast<uint32_t*>(ol_g + (size_t)g1 * DQ + col) = pl;
    }
}

// ---------------------------------------------------------------------------
extern "C" void kernel_launch(void* const* d_in, const int* in_sizes, int n_in,
                              void* d_out, int out_size)
{
    const float* hidden    = (const float*)d_in[0];
    const int*   positions = (const int*)  d_in[1];
    const int*   sort_idx  = (const int*)  d_in[2];
    const float* q_proj_w  = (const float*)d_in[3];
    const float* o_proj_w  = (const float*)d_in[4];
    const float* k_w       = (const float*)d_in[5];
    const float* v_w       = (const float*)d_in[6];
    const float* q_norm_w  = (const float*)d_in[7];
    const float* k_norm_w  = (const float*)d_in[8];
    float* out = (float*)d_out;

    float *qp, *kp, *vp;
    bf16 *hh, *hl, *oh, *ol, *qh, *ql, *kh2, *kl2, *vh, *vl;
    bf16 *wqh, *wql, *woh, *wol, *wkh, *wkl, *wvh, *wvl;
    cudaGetSymbolAddress((void**)&qp, g_q);
    cudaGetSymbolAddress((void**)&kp, g_k);
    cudaGetSymbolAddress((void**)&vp, g_v);
    cudaGetSymbolAddress((void**)&hh, g_hh);
    cudaGetSymbolAddress((void**)&hl, g_hl);
    cudaGetSymbolAddress((void**)&oh, g_oh);
    cudaGetSymbolAddress((void**)&ol, g_ol);
    cudaGetSymbolAddress((void**)&qh, g_qh);
    cudaGetSymbolAddress((void**)&ql, g_ql);
    cudaGetSymbolAddress((void**)&kh2, g_kh2);
    cudaGetSymbolAddress((void**)&kl2, g_kl2);
    cudaGetSymbolAddress((void**)&vh, g_vh);
    cudaGetSymbolAddress((void**)&vl, g_vl);
    cudaGetSymbolAddress((void**)&wqh, g_wq_h);
    cudaGetSymbolAddress((void**)&wql, g_wq_l);
    cudaGetSymbolAddress((void**)&woh, g_wo_h);
    cudaGetSymbolAddress((void**)&wol, g_wo_l);
    cudaGetSymbolAddress((void**)&wkh, g_wk_h);
    cudaGetSymbolAddress((void**)&wkl, g_wk_l);
    cudaGetSymbolAddress((void**)&wvh, g_wv_h);
    cudaGetSymbolAddress((void**)&wvl, g_wv_l);

    cudaFuncSetAttribute(gemm_mma, cudaFuncAttributeMaxDynamicSharedMemorySize, GEMM_SMEM);
    cudaFuncSetAttribute(attn_mma, cudaFuncAttributeMaxDynamicSharedMemorySize, ASMEM);

    // weight transposes + bf16 hi/lo split  ([N][K] layout)
    transpose_split<<<dim3(DQ / 32, HID / 32, NE), dim3(32, 8)>>>(q_proj_w, wqh, wql, HID, DQ);
    transpose_split<<<dim3(HID / 32, DQ / 32, NE), dim3(32, 8)>>>(o_proj_w, woh, wol, DQ, HID);
    transpose_split<<<dim3(DKV / 32, HID / 32, 1), dim3(32, 8)>>>(k_w, wkh, wkl, HID, DKV);
    transpose_split<<<dim3(DKV / 32, HID / 32, 1), dim3(32, 8)>>>(v_w, wvh, wvl, HID, DKV);

    // activation split
    split_act<<<(NTOK * HID / 4 + 255) / 256, 256>>>(hidden, hh, hl, NTOK * HID / 4);

    // projections (fp32 outputs)
    gemm_mma<<<dim3(DQ / 128, CHUNK / 128, NE), 256, GEMM_SMEM>>>(
        hh, hl, wqh, wql, qp, sort_idx, HID, DQ, CHUNK);
    gemm_mma<<<dim3(DKV / 128, NTOK / 128, 1), 256, GEMM_SMEM>>>(
        hh, hl, wkh, wkl, kp, nullptr, HID, DKV, NTOK);
    gemm_mma<<<dim3(DKV / 128, NTOK / 128, 1), 256, GEMM_SMEM>>>(
        hh, hl, wvh, wvl, vp, nullptr, HID, DKV, NTOK);

    // RMSNorm + RoPE, writing bf16 splits (q pre-scaled by 1/sqrt(HD))
    rmsnorm_rope_split<<<(NTOK * NH) / 8, 256>>>(qp, q_norm_w, positions, NH, 0.125f, qh, ql);
    rmsnorm_rope_split<<<(NTOK * NKV) / 8, 256>>>(kp, k_norm_w, positions, NKV, 1.0f, kh2, kl2);
    split_act<<<(NTOK * DKV / 4 + 255) / 256, 256>>>(vp, vh, vl, NTOK * DKV / 4);

    // tensor-core causal GQA flash attention -> bf16 split output
    attn_mma<<<dim3(NTOK / AQ, NH), 256, ASMEM>>>(
        qh, ql, kh2, kl2, vh, vl, positions, oh, ol);

    // out = routed_proj(o, o_proj_w, sort_idx)
    gemm_mma<<<dim3(HID / 128, CHUNK / 128, NE), 256, GEMM_SMEM>>>(
        oh, ol, woh, wol, out, sort_idx, DQ, HID, CHUNK);
}

// round 5
// speedup vs baseline: 4.1611x; 1.2330x over previous
#include <cuda_runtime.h>
#include <cuda_bf16.h>
#include <cstdint>
#include <math.h>

// Problem constants
#define NTOK 2048
#define HID 2048
#define NH 32
#define NKV 8
#define HD 64
#define NE 4
#define CHUNK (NTOK / NE)   // 512
#define DQ (NH * HD)        // 2048
#define DKV (NKV * HD)      // 512
#define DKV2 (2 * DKV)      // 1024 (k|v fused)

typedef __nv_bfloat16 bf16;

// Scratch (device globals: allocation-free rule)
__device__ float g_q[(size_t)NTOK * DQ];
__device__ float g_kv[(size_t)NTOK * DKV2];     // [tok][k(512) | v(512)]

__device__ bf16 g_hh[(size_t)NTOK * HID];
__device__ bf16 g_hl[(size_t)NTOK * HID];
__device__ bf16 g_oh[(size_t)NTOK * DQ];
__device__ bf16 g_ol[(size_t)NTOK * DQ];

__device__ bf16 g_qh[(size_t)NTOK * DQ];
__device__ bf16 g_ql[(size_t)NTOK * DQ];
__device__ bf16 g_kh2[(size_t)NTOK * DKV];
__device__ bf16 g_kl2[(size_t)NTOK * DKV];
__device__ bf16 g_vh[(size_t)NTOK * DKV];
__device__ bf16 g_vl[(size_t)NTOK * DKV];

__device__ bf16 g_wq_h[(size_t)NE * HID * DQ];   // [E][DQ][HID]
__device__ bf16 g_wq_l[(size_t)NE * HID * DQ];
__device__ bf16 g_wo_h[(size_t)NE * DQ * HID];   // [E][HID][DQ]
__device__ bf16 g_wo_l[(size_t)NE * DQ * HID];
__device__ bf16 g_wkv_h[(size_t)DKV2 * HID];     // [k rows 0-511 | v rows 512-1023][HID]
__device__ bf16 g_wkv_l[(size_t)DKV2 * HID];

// ---------------------------------------------------------------------------
__device__ __forceinline__ uint32_t smem_u32(const void* p) {
    uint32_t a;
    asm("{ .reg .u64 t; cvta.to.shared.u64 t, %1; cvt.u32.u64 %0, t; }"
        : "=r"(a) : "l"(p));
    return a;
}

#define CP16(dst, src) \
    asm volatile("cp.async.cg.shared.global [%0], [%1], 16;" \
        :: "r"(dst), "l"(src) : "memory")
#define CP_COMMIT() asm volatile("cp.async.commit_group;" ::: "memory")

#define MMA16816(d, a, b0, b1) \
    asm volatile("mma.sync.aligned.m16n8k16.row.col.f32.bf16.bf16.f32 " \
        "{%0,%1,%2,%3}, {%4,%5,%6,%7}, {%8,%9}, {%0,%1,%2,%3};" \
        : "+f"((d)[0]), "+f"((d)[1]), "+f"((d)[2]), "+f"((d)[3]) \
        : "r"((a)[0]), "r"((a)[1]), "r"((a)[2]), "r"((a)[3]), "r"(b0), "r"(b1))

#define LDSM_4(r0, r1, r2, r3, a) \
    asm volatile("ldmatrix.sync.aligned.m8n8.x4.shared.b16 {%0,%1,%2,%3}, [%4];" \
        : "=r"(r0), "=r"(r1), "=r"(r2), "=r"(r3) : "r"(a))

#define LDSM_T4(r0, r1, r2, r3, a) \
    asm volatile("ldmatrix.sync.aligned.m8n8.x4.trans.shared.b16 {%0,%1,%2,%3}, [%4];" \
        : "=r"(r0), "=r"(r1), "=r"(r2), "=r"(r3) : "r"(a))

__device__ __forceinline__ void bf_split(float f, bf16& h, bf16& l) {
    h = __float2bfloat16(f);
    l = __float2bfloat16(f - __bfloat162float(h));
}

__device__ __forceinline__ void splitpack2(float a, float b, uint32_t& hi, uint32_t& lo) {
    bf16 ha, la, hb, lb;
    bf_split(a, ha, la);
    bf_split(b, hb, lb);
    hi = ((uint32_t)__bfloat16_as_ushort(hb) << 16) | __bfloat16_as_ushort(ha);
    lo = ((uint32_t)__bfloat16_as_ushort(lb) << 16) | __bfloat16_as_ushort(la);
}

// ---------------------------------------------------------------------------
// Weight transpose + bf16 split
// ---------------------------------------------------------------------------
__global__ void transpose_split(const float* __restrict__ W,
                                bf16* __restrict__ Hi, bf16* __restrict__ Lo,
                                int R, int C) {
    __shared__ float t[32][33];
    const float* Wp = W + (size_t)blockIdx.z * R * C;
    bf16* Hp = Hi + (size_t)blockIdx.z * R * C;
    bf16* Lp = Lo + (size_t)blockIdx.z * R * C;
    int x = blockIdx.x * 32 + threadIdx.x;
    int y = blockIdx.y * 32 + threadIdx.y;
#pragma unroll
    for (int i = 0; i < 32; i += 8)
        t[threadIdx.y + i][threadIdx.x] = Wp[(size_t)(y + i) * C + x];
    __syncthreads();
    int r2 = blockIdx.y * 32 + threadIdx.x;
    int c2 = blockIdx.x * 32 + threadIdx.y;
#pragma unroll
    for (int i = 0; i < 32; i += 8) {
        float v = t[threadIdx.x][threadIdx.y + i];
        bf16 h, l;
        bf_split(v, h, l);
        Hp[(size_t)(c2 + i) * R + r2] = h;
        Lp[(size_t)(c2 + i) * R + r2] = l;
    }
}

__global__ void split_act(const float* __restrict__ X,
                          bf16* __restrict__ Hi, bf16* __restrict__ Lo, int n4) {
    int i = blockIdx.x * blockDim.x + threadIdx.x;
    if (i >= n4) return;
    float4 v = reinterpret_cast<const float4*>(X)[i];
    bf16 h[4], l[4];
    bf_split(v.x, h[0], l[0]); bf_split(v.y, h[1], l[1]);
    bf_split(v.z, h[2], l[2]); bf_split(v.w, h[3], l[3]);
    reinterpret_cast<uint2*>(Hi)[i] = *reinterpret_cast<uint2*>(h);
    reinterpret_cast<uint2*>(Lo)[i] = *reinterpret_cast<uint2*>(l);
}

// split v columns (512..1023) of g_kv into [NTOK][DKV] hi/lo
__global__ void split_v(const float* __restrict__ KV,
                        bf16* __restrict__ Hi, bf16* __restrict__ Lo) {
    int i = blockIdx.x * blockDim.x + threadIdx.x;
    if (i >= NTOK * DKV / 4) return;
    int r = i / (DKV / 4);
    int c = i % (DKV / 4);
    float4 v = *reinterpret_cast<const float4*>(KV + (size_t)r * DKV2 + DKV + c * 4);
    bf16 h[4], l[4];
    bf_split(v.x, h[0], l[0]); bf_split(v.y, h[1], l[1]);
    bf_split(v.z, h[2], l[2]); bf_split(v.w, h[3], l[3]);
    *reinterpret_cast<uint2*>(Hi + (size_t)r * DKV + c * 4) = *reinterpret_cast<uint2*>(h);
    *reinterpret_cast<uint2*>(Lo + (size_t)r * DKV + c * 4) = *reinterpret_cast<uint2*>(l);
}

// ---------------------------------------------------------------------------
// bf16x3 mma.sync GEMM with optional row gather/scatter, ldmatrix frags.
// ---------------------------------------------------------------------------
#define LDT 40
#define OPE (128 * LDT)
#define STAGE_E (4 * OPE)
#define GEMM_SMEM (1024 + 2 * STAGE_E * 2)

__device__ __forceinline__ void issue_tile(
    uint32_t sB, int s, int kb,
    const bf16* __restrict__ Agh, const bf16* __restrict__ Agl,
    const bf16* __restrict__ Bgh, const bf16* __restrict__ Bgl,
    const int* __restrict__ rows, int n0, int K, int tid)
{
#pragma unroll
    for (int rep = 0; rep < 2; rep++) {
        int f = tid + rep * 256;
        int m = f >> 2;
        int q = f & 3;
        uint32_t doff = sB + (uint32_t)s * (STAGE_E * 2) + m * (LDT * 2) + q * 16;
        size_t asrc = (size_t)rows[m] * K + kb + q * 8;
        size_t bsrc = (size_t)(n0 + m) * K + kb + q * 8;
        CP16(doff,                Agh + asrc);
        CP16(doff + OPE * 2,      Agl + asrc);
        CP16(doff + OPE * 4,      Bgh + bsrc);
        CP16(doff + OPE * 6,      Bgl + bsrc);
    }
}

__global__ void __launch_bounds__(256, 2) gemm_mma(
    const bf16* __restrict__ Agh, const bf16* __restrict__ Agl,
    const bf16* __restrict__ Bgh, const bf16* __restrict__ Bgl,
    float* __restrict__ C, const int* __restrict__ idx,
    int K, int Nd, int chunk)
{
    extern __shared__ char smc[];
    int* rows = (int*)smc;
    bf16* S = (bf16*)(smc + 1024);
    const uint32_t sB = smem_u32(S);

    const int tid = threadIdx.x;
    const int wid = tid >> 5;
    const int lane = tid & 31;
    const int m0 = blockIdx.y * 128;
    const int n0 = blockIdx.x * 128;
    const int z = blockIdx.z;
    const bf16* Bh_g = Bgh + (size_t)z * K * Nd;
    const bf16* Bl_g = Bgl + (size_t)z * K * Nd;

    if (tid < 128) {
        int lr = z * chunk + m0 + tid;
        rows[tid] = idx ? idx[lr] : lr;
    }
    __syncthreads();

    const int wm = (wid & 3) * 32;
    const int wn = (wid >> 2) * 64;

    // per-lane ldmatrix byte offsets
    const uint32_t lnA = ((((lane >> 3) & 1) * 8 + (lane & 7)) * LDT + (lane >> 4) * 8) * 2;
    const uint32_t lnB = (((lane >> 4) * 8 + (lane & 7)) * LDT + ((lane >> 3) & 1) * 8) * 2;

    float acc[2][8][4];
#pragma unroll
    for (int a = 0; a < 2; a++)
#pragma unroll
        for (int b = 0; b < 8; b++)
#pragma unroll
            for (int c = 0; c < 4; c++) acc[a][b][c] = 0.f;

    const int nkt = K / 32;
    issue_tile(sB, 0, 0, Agh, Agl, Bh_g, Bl_g, rows, n0, K, tid); CP_COMMIT();
    issue_tile(sB, 1, 32, Agh, Agl, Bh_g, Bl_g, rows, n0, K, tid); CP_COMMIT();

    for (int kt = 0; kt < nkt; kt++) {
        if (kt + 1 < nkt) asm volatile("cp.async.wait_group 1;" ::: "memory");
        else              asm volatile("cp.async.wait_group 0;" ::: "memory");
        __syncthreads();

        const int s = kt & 1;
        const uint32_t sb_s = sB + (uint32_t)s * (STAGE_E * 2);

#pragma unroll
        for (int ks = 0; ks < 32; ks += 16) {
            uint32_t ah[2][4], al[2][4];
            uint32_t abase = sb_s + (uint32_t)(wm * LDT + ks) * 2 + lnA;
#pragma unroll
            for (int mi = 0; mi < 2; mi++) {
                LDSM_4(ah[mi][0], ah[mi][1], ah[mi][2], ah[mi][3],
                       abase + mi * (16 * LDT * 2));
                LDSM_4(al[mi][0], al[mi][1], al[mi][2], al[mi][3],
                       abase + mi * (16 * LDT * 2) + OPE * 2);
            }
#pragma unroll
            for (int np = 0; np < 4; np++) {
                uint32_t boff = sb_s + OPE * 4
                              + (uint32_t)((wn + np * 16) * LDT + ks) * 2 + lnB;
                uint32_t bh0, bh1, bh2, bh3, bl0, bl1, bl2, bl3;
                LDSM_4(bh0, bh1, bh2, bh3, boff);
                LDSM_4(bl0, bl1, bl2, bl3, boff + OPE * 2);
#pragma unroll
                for (int mi = 0; mi < 2; mi++) {
                    MMA16816(acc[mi][2 * np], ah[mi], bh0, bh1);
                    MMA16816(acc[mi][2 * np], ah[mi], bl0, bl1);
                    MMA16816(acc[mi][2 * np], al[mi], bh0, bh1);
                    MMA16816(acc[mi][2 * np + 1], ah[mi], bh2, bh3);
                    MMA16816(acc[mi][2 * np + 1], ah[mi], bl2, bl3);
                    MMA16816(acc[mi][2 * np + 1], al[mi], bh2, bh3);
                }
            }
        }
        __syncthreads();
        if (kt + 2 < nkt) {
            issue_tile(sB, s, (kt + 2) * 32, Agh, Agl, Bh_g, Bl_g, rows, n0, K, tid);
            CP_COMMIT();
        }
    }

    const int rq = lane >> 2;
    const int cq = (lane & 3) * 2;
#pragma unroll
    for (int mi = 0; mi < 2; mi++) {
        int r = wm + mi * 16 + rq;
        size_t gr0 = (size_t)rows[r];
        size_t gr1 = (size_t)rows[r + 8];
#pragma unroll
        for (int ni = 0; ni < 8; ni++) {
            int col = n0 + wn + ni * 8 + cq;
            *reinterpret_cast<float2*>(&C[gr0 * Nd + col]) =
                make_float2(acc[mi][ni][0], acc[mi][ni][1]);
            *reinterpret_cast<float2*>(&C[gr1 * Nd + col]) =
                make_float2(acc[mi][ni][2], acc[mi][ni][3]);
        }
    }
}

// ---------------------------------------------------------------------------
// RMSNorm + NeoX RoPE, writing bf16 hi/lo splits (scaled by sc).
// ---------------------------------------------------------------------------
__global__ void rmsnorm_rope_split(const float* __restrict__ x, int instride,
                                   const float* __restrict__ w,
                                   const int* __restrict__ pos, int n_heads,
                                   float sc, bf16* __restrict__ Hi,
                                   bf16* __restrict__ Lo)
{
    int warp = (blockIdx.x * blockDim.x + threadIdx.x) >> 5;
    int lane = threadIdx.x & 31;
    int total = NTOK * n_heads;
    if (warp >= total) return;
    int t = warp / n_heads;
    int h = warp - t * n_heads;

    const float* row = x + (size_t)t * instride + (size_t)h * HD;
    float x1 = row[lane];
    float x2 = row[lane + 32];
    float ss = x1 * x1 + x2 * x2;
#pragma unroll
    for (int o = 16; o; o >>= 1) ss += __shfl_xor_sync(0xffffffff, ss, o);
    float r = rsqrtf(ss * (1.0f / 64.0f) + 1e-6f);
    float y1 = x1 * r * w[lane];
    float y2 = x2 * r * w[lane + 32];

    float p = (float)pos[t];
    float inv = powf(10000.0f, -(float)lane * (1.0f / 32.0f));
    float f = p * inv;
    float s, c;
    sincosf(f, &s, &c);
    float o1 = (y1 * c - y2 * s) * sc;
    float o2 = (y2 * c + y1 * s) * sc;

    size_t base = (size_t)t * (n_heads * HD) + (size_t)h * HD;
    bf16 h1, l1, h2, l2;
    bf_split(o1, h1, l1);
    bf_split(o2, h2, l2);
    Hi[base + lane] = h1;      Lo[base + lane] = l1;
    Hi[base + lane + 32] = h2; Lo[base + lane + 32] = l2;
}

// ---------------------------------------------------------------------------
// Tensor-core flash attention (causal GQA), bf16x3 + ldmatrix K frags.
// ---------------------------------------------------------------------------
#define AQ 128
#define AK 64
#define LDK 72
#define QSM (AQ * LDK)
#define KSM (AK * LDK)
#define ASMEM ((2 * QSM + 8 * KSM) * 2 + 2 * AK * 4)

__device__ __forceinline__ void attn_issue(
    uint32_t sbase, int s, int kt, int kvh, int tid,
    const bf16* __restrict__ kh_g, const bf16* __restrict__ kl_g,
    const bf16* __restrict__ vh_g, const bf16* __restrict__ vl_g,
    const int* __restrict__ pos, int* __restrict__ kpos_sm)
{
#pragma unroll
    for (int i = 0; i < 8; i++) {
        int f = tid + i * 256;
        int arr = f >> 9;
        int r = (f >> 3) & 63;
        int seg = f & 7;
        const bf16* src = (arr == 0) ? kh_g : (arr == 1) ? kl_g
                        : (arr == 2) ? vh_g : vl_g;
        uint32_t dst = sbase + (uint32_t)(2 * QSM + (s * 4 + arr) * KSM + r * LDK) * 2
                     + seg * 16;
        CP16(dst, src + (size_t)(kt * AK + r) * DKV + (size_t)kvh * HD + seg * 8);
    }
    if (tid < AK) kpos_sm[s * AK + tid] = pos[kt * AK + tid];
    CP_COMMIT();
}

__global__ void __launch_bounds__(256, 1) attn_mma(
    const bf16* __restrict__ qh_g, const bf16* __restrict__ ql_g,
    const bf16* __restrict__ kh_g, const bf16* __restrict__ kl_g,
    const bf16* __restrict__ vh_g, const bf16* __restrict__ vl_g,
    const int* __restrict__ pos,
    bf16* __restrict__ oh_g, bf16* __restrict__ ol_g)
{
    extern __shared__ char sm[];
    const uint32_t sbase = smem_u32(sm);
    int* kpos = (int*)(sm + (size_t)(2 * QSM + 8 * KSM) * 2);

    const int tid = threadIdx.x;
    const int w = tid >> 5;
    const int l = tid & 31;
    const int qt = gridDim.x - 1 - blockIdx.x;   // heavy tiles first
    const int h = blockIdx.y;
    const int kvh = h >> 2;
    const int q0 = qt * AQ;
    const int ntile = 2 * qt + 2;

    attn_issue(sbase, 0, 0, kvh, tid, kh_g, kl_g, vh_g, vl_g, pos, kpos);
    attn_issue(sbase, 1, 1, kvh, tid, kh_g, kl_g, vh_g, vl_g, pos, kpos);

    // stage Q (hi, lo) into smem, padded rows
#pragma unroll
    for (int i = 0; i < 4; i++) {
        int f = tid + i * 256;
        int r = f >> 3;
        int seg = f & 7;
        uint4 v1 = *reinterpret_cast<const uint4*>(
            qh_g + (size_t)(q0 + r) * DQ + (size_t)h * HD + seg * 8);
        *reinterpret_cast<uint4*>(sm + (size_t)(r * LDK) * 2 + seg * 16) = v1;
        uint4 v2 = *reinterpret_cast<const uint4*>(
            ql_g + (size_t)(q0 + r) * DQ + (size_t)h * HD + seg * 8);
        *reinterpret_cast<uint4*>(sm + (size_t)(QSM + r * LDK) * 2 + seg * 16) = v2;
    }
    __syncthreads();

    const int rq = l >> 2;
    const int cq = l & 3;
    const int row0 = w * 16 + rq;

    const uint32_t* smw = (const uint32_t*)sm;
    uint32_t qfh[4][4], qfl[4][4];
#pragma unroll
    for (int kf = 0; kf < 4; kf++) {
        int b = kf * 8 + cq;
        qfh[kf][0] = smw[row0 * 36 + b];
        qfh[kf][1] = smw[(row0 + 8) * 36 + b];
        qfh[kf][2] = smw[row0 * 36 + b + 4];
        qfh[kf][3] = smw[(row0 + 8) * 36 + b + 4];
        qfl[kf][0] = smw[(QSM / 2) + row0 * 36 + b];
        qfl[kf][1] = smw[(QSM / 2) + (row0 + 8) * 36 + b];
        qfl[kf][2] = smw[(QSM / 2) + row0 * 36 + b + 4];
        qfl[kf][3] = smw[(QSM / 2) + (row0 + 8) * 36 + b + 4];
    }
    const int qp0 = pos[q0 + row0];
    const int qp1 = pos[q0 + row0 + 8];

    float o[8][4];
#pragma unroll
    for (int nf = 0; nf < 8; nf++)
#pragma unroll
        for (int e = 0; e < 4; e++) o[nf][e] = 0.f;
    float m0 = -1e30f, m1 = -1e30f, l0 = 0.f, l1 = 0.f;

    const int lrow16 = l & 15;
    const int lsel = l >> 4;
    // per-lane ldmatrix offset for K (B operand, [key][d] layout)
    const uint32_t lnK = (((l >> 4) * 8 + (l & 7)) * LDK + ((l >> 3) & 1) * 8) * 2;

    for (int kt = 0; kt < ntile; kt++) {
        if (kt + 1 < ntile) asm volatile("cp.async.wait_group 1;" ::: "memory");
        else                asm volatile("cp.async.wait_group 0;" ::: "memory");
        __syncthreads();

        const int s = kt & 1;
        const uint32_t khb = sbase + (uint32_t)(2 * QSM + (s * 4 + 0) * KSM) * 2;
        const uint32_t vhb = sbase + (uint32_t)(2 * QSM + (s * 4 + 2) * KSM) * 2;
        const uint32_t vlb = sbase + (uint32_t)(2 * QSM + (s * 4 + 3) * KSM) * 2;

        float sv[8][4];
#pragma unroll
        for (int nf = 0; nf < 8; nf++)
#pragma unroll
            for (int e = 0; e < 4; e++) sv[nf][e] = 0.f;

        // S = Q K^T (3 terms), K frags via ldmatrix.x4
#pragma unroll
        for (int kf = 0; kf < 4; kf++) {
#pragma unroll
            for (int np = 0; np < 4; np++) {
                uint32_t koff = khb + (uint32_t)(np * 16 * LDK) * 2 + kf * 32 + lnK;
                uint32_t b0, b1, b2, b3, c0, c1, c2, c3;
                LDSM_4(b0, b1, b2, b3, koff);
                LDSM_4(c0, c1, c2, c3, koff + KSM * 2);
                MMA16816(sv[2 * np], qfh[kf], b0, b1);
                MMA16816(sv[2 * np], qfh[kf], c0, c1);
                MMA16816(sv[2 * np], qfl[kf], b0, b1);
                MMA16816(sv[2 * np + 1], qfh[kf], b2, b3);
                MMA16816(sv[2 * np + 1], qfh[kf], c2, c3);
                MMA16816(sv[2 * np + 1], qfl[kf], b2, b3);
            }
        }

        if (kt >= 2 * qt) {
            const int* kp = kpos + s * AK;
#pragma unroll
            for (int nf = 0; nf < 8; nf++) {
                int c = nf * 8 + cq * 2;
                int k0 = kp[c], k1 = kp[c + 1];
                if (k0 > qp0) sv[nf][0] = -1e30f;
                if (k1 > qp0) sv[nf][1] = -1e30f;
                if (k0 > qp1) sv[nf][2] = -1e30f;
                if (k1 > qp1) sv[nf][3] = -1e30f;
            }
        }

        float mt0 = -1e30f, mt1 = -1e30f;
#pragma unroll
        for (int nf = 0; nf < 8; nf++) {
            mt0 = fmaxf(mt0, fmaxf(sv[nf][0], sv[nf][1]));
            mt1 = fmaxf(mt1, fmaxf(sv[nf][2], sv[nf][3]));
        }
        mt0 = fmaxf(mt0, __shfl_xor_sync(0xffffffff, mt0, 1));
        mt0 = fmaxf(mt0, __shfl_xor_sync(0xffffffff, mt0, 2));
        mt1 = fmaxf(mt1, __shfl_xor_sync(0xffffffff, mt1, 1));
        mt1 = fmaxf(mt1, __shfl_xor_sync(0xffffffff, mt1, 2));
        float mn0 = fmaxf(m0, mt0), mn1 = fmaxf(m1, mt1);
        float a0 = __expf(m0 - mn0), a1 = __expf(m1 - mn1);
        m0 = mn0; m1 = mn1;
#pragma unroll
        for (int nf = 0; nf < 8; nf++) {
            o[nf][0] *= a0; o[nf][1] *= a0;
            o[nf][2] *= a1; o[nf][3] *= a1;
        }
        float rs0 = 0.f, rs1 = 0.f;
#pragma unroll
        for (int nf = 0; nf < 8; nf++) {
            sv[nf][0] = __expf(sv[nf][0] - mn0); rs0 += sv[nf][0];
            sv[nf][1] = __expf(sv[nf][1] - mn0); rs0 += sv[nf][1];
            sv[nf][2] = __expf(sv[nf][2] - mn1); rs1 += sv[nf][2];
            sv[nf][3] = __expf(sv[nf][3] - mn1); rs1 += sv[nf][3];
        }
        rs0 += __shfl_xor_sync(0xffffffff, rs0, 1);
        rs0 += __shfl_xor_sync(0xffffffff, rs0, 2);
        rs1 += __shfl_xor_sync(0xffffffff, rs1, 1);
        rs1 += __shfl_xor_sync(0xffffffff, rs1, 2);
        l0 = l0 * a0 + rs0;
        l1 = l1 * a1 + rs1;

        // O += P V (3 terms)
#pragma unroll
        for (int kfk = 0; kfk < 4; kfk++) {
            uint32_t pah[4], pal[4];
            splitpack2(sv[2 * kfk][0], sv[2 * kfk][1], pah[0], pal[0]);
            splitpack2(sv[2 * kfk][2], sv[2 * kfk][3], pah[1], pal[1]);
            splitpack2(sv[2 * kfk + 1][0], sv[2 * kfk + 1][1], pah[2], pal[2]);
            splitpack2(sv[2 * kfk + 1][2], sv[2 * kfk + 1][3], pah[3], pal[3]);

            uint32_t vfh[8][2], vfl[8][2];
#pragma unroll
            for (int nfp = 0; nfp < 4; nfp++) {
                uint32_t off = (uint32_t)((kfk * 16 + lrow16) * LDK
                                          + nfp * 16 + lsel * 8) * 2;
                uint32_t r0, r1, r2, r3;
                LDSM_T4(r0, r1, r2, r3, vhb + off);
                vfh[2 * nfp][0] = r0;     vfh[2 * nfp][1] = r1;
                vfh[2 * nfp + 1][0] = r2; vfh[2 * nfp + 1][1] = r3;
                LDSM_T4(r0, r1, r2, r3, vlb + off);
                vfl[2 * nfp][0] = r0;     vfl[2 * nfp][1] = r1;
                vfl[2 * nfp + 1][0] = r2; vfl[2 * nfp + 1][1] = r3;
            }
#pragma unroll
            for (int nf = 0; nf < 8; nf++) {
                MMA16816(o[nf], pah, vfh[nf][0], vfh[nf][1]);
                MMA16816(o[nf], pah, vfl[nf][0], vfl[nf][1]);
                MMA16816(o[nf], pal, vfh[nf][0], vfh[nf][1]);
            }
        }

        __syncthreads();
        if (kt + 2 < ntile)
            attn_issue(sbase, s, kt + 2, kvh, tid, kh_g, kl_g, vh_g, vl_g, pos, kpos);
    }

    float i0 = 1.f / l0, i1 = 1.f / l1;
    int g0 = q0 + w * 16 + rq;
    int g1 = g0 + 8;
#pragma unroll
    for (int nf = 0; nf < 8; nf++) {
        int col = h * HD + nf * 8 + cq * 2;
        uint32_t ph, pl;
        splitpack2(o[nf][0] * i0, o[nf][1] * i0, ph, pl);
        *reinterpret_cast<uint32_t*>(oh_g + (size_t)g0 * DQ + col) = ph;
        *reinterpret_cast<uint32_t*>(ol_g + (size_t)g0 * DQ + col) = pl;
        splitpack2(o[nf][2] * i1, o[nf][3] * i1, ph, pl);
        *reinterpret_cast<uint32_t*>(oh_g + (size_t)g1 * DQ + col) = ph;
        *reinterpret_cast<uint32_t*>(ol_g + (size_t)g1 * DQ + col) = pl;
    }
}

// ---------------------------------------------------------------------------
extern "C" void kernel_launch(void* const* d_in, const int* in_sizes, int n_in,
                              void* d_out, int out_size)
{
    const float* hidden    = (const float*)d_in[0];
    const int*   positions = (const int*)  d_in[1];
    const int*   sort_idx  = (const int*)  d_in[2];
    const float* q_proj_w  = (const float*)d_in[3];
    const float* o_proj_w  = (const float*)d_in[4];
    const float* k_w       = (const float*)d_in[5];
    const float* v_w       = (const float*)d_in[6];
    const float* q_norm_w  = (const float*)d_in[7];
    const float* k_norm_w  = (const float*)d_in[8];
    float* out = (float*)d_out;

    float *qp, *kvp;
    bf16 *hh, *hl, *oh, *ol, *qh, *ql, *kh2, *kl2, *vh, *vl;
    bf16 *wqh, *wql, *woh, *wol, *wkvh, *wkvl;
    cudaGetSymbolAddress((void**)&qp, g_q);
    cudaGetSymbolAddress((void**)&kvp, g_kv);
    cudaGetSymbolAddress((void**)&hh, g_hh);
    cudaGetSymbolAddress((void**)&hl, g_hl);
    cudaGetSymbolAddress((void**)&oh, g_oh);
    cudaGetSymbolAddress((void**)&ol, g_ol);
    cudaGetSymbolAddress((void**)&qh, g_qh);
    cudaGetSymbolAddress((void**)&ql, g_ql);
    cudaGetSymbolAddress((void**)&kh2, g_kh2);
    cudaGetSymbolAddress((void**)&kl2, g_kl2);
    cudaGetSymbolAddress((void**)&vh, g_vh);
    cudaGetSymbolAddress((void**)&vl, g_vl);
    cudaGetSymbolAddress((void**)&wqh, g_wq_h);
    cudaGetSymbolAddress((void**)&wql, g_wq_l);
    cudaGetSymbolAddress((void**)&woh, g_wo_h);
    cudaGetSymbolAddress((void**)&wol, g_wo_l);
    cudaGetSymbolAddress((void**)&wkvh, g_wkv_h);
    cudaGetSymbolAddress((void**)&wkvl, g_wkv_l);

    cudaFuncSetAttribute(gemm_mma, cudaFuncAttributeMaxDynamicSharedMemorySize, GEMM_SMEM);
    cudaFuncSetAttribute(attn_mma, cudaFuncAttributeMaxDynamicSharedMemorySize, ASMEM);

    // weight transposes + bf16 split ([N][K] layout; k|v stacked)
    transpose_split<<<dim3(DQ / 32, HID / 32, NE), dim3(32, 8)>>>(q_proj_w, wqh, wql, HID, DQ);
    transpose_split<<<dim3(HID / 32, DQ / 32, NE), dim3(32, 8)>>>(o_proj_w, woh, wol, DQ, HID);
    transpose_split<<<dim3(DKV / 32, HID / 32, 1), dim3(32, 8)>>>(k_w, wkvh, wkvl, HID, DKV);
    transpose_split<<<dim3(DKV / 32, HID / 32, 1), dim3(32, 8)>>>(
        v_w, wkvh + (size_t)DKV * HID, wkvl + (size_t)DKV * HID, HID, DKV);

    split_act<<<(NTOK * HID / 4 + 255) / 256, 256>>>(hidden, hh, hl, NTOK * HID / 4);

    // q proj (routed) and fused k|v proj
    gemm_mma<<<dim3(DQ / 128, CHUNK / 128, NE), 256, GEMM_SMEM>>>(
        hh, hl, wqh, wql, qp, sort_idx, HID, DQ, CHUNK);
    gemm_mma<<<dim3(DKV2 / 128, NTOK / 128, 1), 256, GEMM_SMEM>>>(
        hh, hl, wkvh, wkvl, kvp, nullptr, HID, DKV2, NTOK);

    // RMSNorm + RoPE -> bf16 splits (q pre-scaled 1/8); v split
    rmsnorm_rope_split<<<(NTOK * NH) / 8, 256>>>(qp, DQ, q_norm_w, positions, NH, 0.125f, qh, ql);
    rmsnorm_rope_split<<<(NTOK * NKV) / 8, 256>>>(kvp, DKV2, k_norm_w, positions, NKV, 1.0f, kh2, kl2);
    split_v<<<(NTOK * DKV / 4 + 255) / 256, 256>>>(kvp, vh, vl);

    // tensor-core causal GQA flash attention
    attn_mma<<<dim3(NTOK / AQ, NH), 256, ASMEM>>>(
        qh, ql, kh2, kl2, vh, vl, positions, oh, ol);

    // o proj (routed)
    gemm_mma<<<dim3(HID / 128, CHUNK / 128, NE), 256, GEMM_SMEM>>>(
        oh, ol, woh, wol, out, sort_idx, DQ, HID, CHUNK);
}

// round 6
// speedup vs baseline: 4.3804x; 1.0527x over previous
#include <cuda_runtime.h>
#include <cuda_bf16.h>
#include <cstdint>
#include <math.h>

// Problem constants
#define NTOK 2048
#define HID 2048
#define NH 32
#define NKV 8
#define HD 64
#define NE 4
#define CHUNK (NTOK / NE)   // 512
#define DQ (NH * HD)        // 2048
#define DKV (NKV * HD)      // 512
#define DKV2 (2 * DKV)      // 1024

typedef __nv_bfloat16 bf16;

// Scratch
__device__ float g_q[(size_t)NTOK * DQ];
__device__ float g_kv[(size_t)NTOK * DKV2];

__device__ bf16 g_hh[(size_t)NTOK * HID];
__device__ bf16 g_hl[(size_t)NTOK * HID];
__device__ bf16 g_oh[(size_t)NTOK * DQ];
__device__ bf16 g_ol[(size_t)NTOK * DQ];

__device__ bf16 g_qh[(size_t)NTOK * DQ];
__device__ bf16 g_ql[(size_t)NTOK * DQ];
__device__ bf16 g_kh2[(size_t)NTOK * DKV];
__device__ bf16 g_kl2[(size_t)NTOK * DKV];
__device__ bf16 g_vh[(size_t)NTOK * DKV];
__device__ bf16 g_vl[(size_t)NTOK * DKV];

__device__ bf16 g_wq_h[(size_t)NE * HID * DQ];
__device__ bf16 g_wq_l[(size_t)NE * HID * DQ];
__device__ bf16 g_wo_h[(size_t)NE * DQ * HID];
__device__ bf16 g_wo_l[(size_t)NE * DQ * HID];
__device__ bf16 g_wkv_h[(size_t)DKV2 * HID];
__device__ bf16 g_wkv_l[(size_t)DKV2 * HID];

// ---------------------------------------------------------------------------
__device__ __forceinline__ uint32_t smem_u32(const void* p) {
    uint32_t a;
    asm("{ .reg .u64 t; cvta.to.shared.u64 t, %1; cvt.u32.u64 %0, t; }"
        : "=r"(a) : "l"(p));
    return a;
}

#define CP16(dst, src) \
    asm volatile("cp.async.cg.shared.global [%0], [%1], 16;" \
        :: "r"(dst), "l"(src) : "memory")
#define CP_COMMIT() asm volatile("cp.async.commit_group;" ::: "memory")

#define MMA16816(d, a, b0, b1) \
    asm volatile("mma.sync.aligned.m16n8k16.row.col.f32.bf16.bf16.f32 " \
        "{%0,%1,%2,%3}, {%4,%5,%6,%7}, {%8,%9}, {%0,%1,%2,%3};" \
        : "+f"((d)[0]), "+f"((d)[1]), "+f"((d)[2]), "+f"((d)[3]) \
        : "r"((a)[0]), "r"((a)[1]), "r"((a)[2]), "r"((a)[3]), "r"(b0), "r"(b1))

#define LDSM_4(r0, r1, r2, r3, a) \
    asm volatile("ldmatrix.sync.aligned.m8n8.x4.shared.b16 {%0,%1,%2,%3}, [%4];" \
        : "=r"(r0), "=r"(r1), "=r"(r2), "=r"(r3) : "r"(a))

#define LDSM_T4(r0, r1, r2, r3, a) \
    asm volatile("ldmatrix.sync.aligned.m8n8.x4.trans.shared.b16 {%0,%1,%2,%3}, [%4];" \
        : "=r"(r0), "=r"(r1), "=r"(r2), "=r"(r3) : "r"(a))

__device__ __forceinline__ void bf_split(float f, bf16& h, bf16& l) {
    h = __float2bfloat16(f);
    l = __float2bfloat16(f - __bfloat162float(h));
}

__device__ __forceinline__ void splitpack2(float a, float b, uint32_t& hi, uint32_t& lo) {
    bf16 ha, la, hb, lb;
    bf_split(a, ha, la);
    bf_split(b, hb, lb);
    hi = ((uint32_t)__bfloat16_as_ushort(hb) << 16) | __bfloat16_as_ushort(ha);
    lo = ((uint32_t)__bfloat16_as_ushort(lb) << 16) | __bfloat16_as_ushort(la);
}

// ---------------------------------------------------------------------------
// Fused input prep: 4 weight transposes + activation split, one launch.
// ---------------------------------------------------------------------------
__device__ __forceinline__ void transpose_body(
    const float* __restrict__ Wp, bf16* __restrict__ Hp, bf16* __restrict__ Lp,
    int R, int C, int bx, int by, int tid, float* tsh)
{
    int tx = tid & 31, ty = tid >> 5;
    int x = bx * 32 + tx;
    int y = by * 32 + ty;
#pragma unroll
    for (int i = 0; i < 32; i += 8)
        tsh[(ty + i) * 33 + tx] = Wp[(size_t)(y + i) * C + x];
    __syncthreads();
    int r2 = by * 32 + tx;
    int c2 = bx * 32 + ty;
#pragma unroll
    for (int i = 0; i < 32; i += 8) {
        float v = tsh[tx * 33 + (ty + i)];
        bf16 h, l;
        bf_split(v, h, l);
        Hp[(size_t)(c2 + i) * R + r2] = h;
        Lp[(size_t)(c2 + i) * R + r2] = l;
    }
}

__global__ void __launch_bounds__(256) prep_inputs(
    const float* __restrict__ q_proj_w, const float* __restrict__ o_proj_w,
    const float* __restrict__ k_w, const float* __restrict__ v_w,
    const float* __restrict__ hidden,
    bf16* __restrict__ wqh, bf16* __restrict__ wql,
    bf16* __restrict__ woh, bf16* __restrict__ wol,
    bf16* __restrict__ wkvh, bf16* __restrict__ wkvl,
    bf16* __restrict__ hh, bf16* __restrict__ hl)
{
    __shared__ float tsh[32 * 33];
    int b = blockIdx.x;
    int tid = threadIdx.x;

    if (b < 16384) {                       // q_proj_w^T: [E][2048][2048]
        int bz = b >> 12, rem = b & 4095;
        int bx = rem & 63, by = rem >> 6;
        transpose_body(q_proj_w + (size_t)bz * HID * DQ,
                       wqh + (size_t)bz * HID * DQ, wql + (size_t)bz * HID * DQ,
                       HID, DQ, bx, by, tid, tsh);
    } else if (b < 32768) {                // o_proj_w^T
        int bb = b - 16384;
        int bz = bb >> 12, rem = bb & 4095;
        int bx = rem & 63, by = rem >> 6;
        transpose_body(o_proj_w + (size_t)bz * DQ * HID,
                       woh + (size_t)bz * DQ * HID, wol + (size_t)bz * DQ * HID,
                       DQ, HID, bx, by, tid, tsh);
    } else if (b < 33792) {                // k_w^T -> wkv rows [0,512)
        int bb = b - 32768;
        int bx = bb & 15, by = bb >> 4;
        transpose_body(k_w, wkvh, wkvl, HID, DKV, bx, by, tid, tsh);
    } else if (b < 34816) {                // v_w^T -> wkv rows [512,1024)
        int bb = b - 33792;
        int bx = bb & 15, by = bb >> 4;
        transpose_body(v_w, wkvh + (size_t)DKV * HID, wkvl + (size_t)DKV * HID,
                       HID, DKV, bx, by, tid, tsh);
    } else {                               // hidden split
        int i = (b - 34816) * 256 + tid;
        float4 v = reinterpret_cast<const float4*>(hidden)[i];
        bf16 h[4], l[4];
        bf_split(v.x, h[0], l[0]); bf_split(v.y, h[1], l[1]);
        bf_split(v.z, h[2], l[2]); bf_split(v.w, h[3], l[3]);
        reinterpret_cast<uint2*>(hh)[i] = *reinterpret_cast<uint2*>(h);
        reinterpret_cast<uint2*>(hl)[i] = *reinterpret_cast<uint2*>(l);
    }
}

// ---------------------------------------------------------------------------
// bf16x3 mma.sync GEMM body (128x128 tile) + merged q/kv dispatcher.
// ---------------------------------------------------------------------------
#define LDT 40
#define OPE (128 * LDT)
#define STAGE_E (4 * OPE)
#define GEMM_SMEM (1024 + 2 * STAGE_E * 2)

__device__ __forceinline__ void issue_tile(
    uint32_t sB, int s, int kb,
    const bf16* __restrict__ Agh, const bf16* __restrict__ Agl,
    const bf16* __restrict__ Bgh, const bf16* __restrict__ Bgl,
    const int* __restrict__ rows, int n0, int K, int tid)
{
#pragma unroll
    for (int rep = 0; rep < 2; rep++) {
        int f = tid + rep * 256;
        int m = f >> 2;
        int q = f & 3;
        uint32_t doff = sB + (uint32_t)s * (STAGE_E * 2) + m * (LDT * 2) + q * 16;
        size_t asrc = (size_t)rows[m] * K + kb + q * 8;
        size_t bsrc = (size_t)(n0 + m) * K + kb + q * 8;
        CP16(doff,           Agh + asrc);
        CP16(doff + OPE * 2, Agl + asrc);
        CP16(doff + OPE * 4, Bgh + bsrc);
        CP16(doff + OPE * 6, Bgl + bsrc);
    }
}

__device__ __forceinline__ void gemm_body(
    const bf16* __restrict__ Agh, const bf16* __restrict__ Agl,
    const bf16* __restrict__ Bh_g, const bf16* __restrict__ Bl_g,
    float* __restrict__ C, const int* __restrict__ idx,
    int K, int Nd, int chunk, int m0, int n0, int zchunk, char* smc)
{
    int* rows = (int*)smc;
    const uint32_t sB = smem_u32(smc + 1024);

    const int tid = threadIdx.x;
    const int wid = tid >> 5;
    const int lane = tid & 31;

    if (tid < 128) {
        int lr = zchunk + m0 + tid;
        rows[tid] = idx ? idx[lr] : lr;
    }
    __syncthreads();

    const int wm = (wid & 3) * 32;
    const int wn = (wid >> 2) * 64;
    const uint32_t lnA = ((((lane >> 3) & 1) * 8 + (lane & 7)) * LDT + (lane >> 4) * 8) * 2;
    const uint32_t lnB = (((lane >> 4) * 8 + (lane & 7)) * LDT + ((lane >> 3) & 1) * 8) * 2;

    float acc[2][8][4];
#pragma unroll
    for (int a = 0; a < 2; a++)
#pragma unroll
        for (int b = 0; b < 8; b++)
#pragma unroll
            for (int c = 0; c < 4; c++) acc[a][b][c] = 0.f;

    const int nkt = K / 32;
    issue_tile(sB, 0, 0, Agh, Agl, Bh_g, Bl_g, rows, n0, K, tid); CP_COMMIT();
    issue_tile(sB, 1, 32, Agh, Agl, Bh_g, Bl_g, rows, n0, K, tid); CP_COMMIT();

    for (int kt = 0; kt < nkt; kt++) {
        if (kt + 1 < nkt) asm volatile("cp.async.wait_group 1;" ::: "memory");
        else              asm volatile("cp.async.wait_group 0;" ::: "memory");
        __syncthreads();

        const int s = kt & 1;
        const uint32_t sb_s = sB + (uint32_t)s * (STAGE_E * 2);

#pragma unroll
        for (int ks = 0; ks < 32; ks += 16) {
            uint32_t ah[2][4], al[2][4];
            uint32_t abase = sb_s + (uint32_t)(wm * LDT + ks) * 2 + lnA;
#pragma unroll
            for (int mi = 0; mi < 2; mi++) {
                LDSM_4(ah[mi][0], ah[mi][1], ah[mi][2], ah[mi][3],
                       abase + mi * (16 * LDT * 2));
                LDSM_4(al[mi][0], al[mi][1], al[mi][2], al[mi][3],
                       abase + mi * (16 * LDT * 2) + OPE * 2);
            }
#pragma unroll
            for (int np = 0; np < 4; np++) {
                uint32_t boff = sb_s + OPE * 4
                              + (uint32_t)((wn + np * 16) * LDT + ks) * 2 + lnB;
                uint32_t bh0, bh1, bh2, bh3, bl0, bl1, bl2, bl3;
                LDSM_4(bh0, bh1, bh2, bh3, boff);
                LDSM_4(bl0, bl1, bl2, bl3, boff + OPE * 2);
#pragma unroll
                for (int mi = 0; mi < 2; mi++) {
                    MMA16816(acc[mi][2 * np], ah[mi], bh0, bh1);
                    MMA16816(acc[mi][2 * np], ah[mi], bl0, bl1);
                    MMA16816(acc[mi][2 * np], al[mi], bh0, bh1);
                    MMA16816(acc[mi][2 * np + 1], ah[mi], bh2, bh3);
                    MMA16816(acc[mi][2 * np + 1], ah[mi], bl2, bl3);
                    MMA16816(acc[mi][2 * np + 1], al[mi], bh2, bh3);
                }
            }
        }
        __syncthreads();
        if (kt + 2 < nkt) {
            issue_tile(sB, s, (kt + 2) * 32, Agh, Agl, Bh_g, Bl_g, rows, n0, K, tid);
            CP_COMMIT();
        }
    }

    const int rq = lane >> 2;
    const int cq = (lane & 3) * 2;
#pragma unroll
    for (int mi = 0; mi < 2; mi++) {
        int r = wm + mi * 16 + rq;
        size_t gr0 = (size_t)rows[r];
        size_t gr1 = (size_t)rows[r + 8];
#pragma unroll
        for (int ni = 0; ni < 8; ni++) {
            int col = n0 + wn + ni * 8 + cq;
            *reinterpret_cast<float2*>(&C[gr0 * Nd + col]) =
                make_float2(acc[mi][ni][0], acc[mi][ni][1]);
            *reinterpret_cast<float2*>(&C[gr1 * Nd + col]) =
                make_float2(acc[mi][ni][2], acc[mi][ni][3]);
        }
    }
}

// Merged q-proj (bid<256) + kv-proj (bid>=256)
__global__ void __launch_bounds__(256, 2) gemm_qkv(
    const bf16* __restrict__ hh, const bf16* __restrict__ hl,
    const bf16* __restrict__ wqh, const bf16* __restrict__ wql,
    const bf16* __restrict__ wkvh, const bf16* __restrict__ wkvl,
    float* __restrict__ qp, float* __restrict__ kvp,
    const int* __restrict__ sort_idx)
{
    extern __shared__ char smc[];
    int bid = blockIdx.x;
    if (bid < 256) {
        int x = bid & 15, y = (bid >> 4) & 3, z = bid >> 6;
        gemm_body(hh, hl,
                  wqh + (size_t)z * HID * DQ, wql + (size_t)z * HID * DQ,
                  qp, sort_idx, HID, DQ, CHUNK, y * 128, x * 128, z * CHUNK, smc);
    } else {
        int bb = bid - 256;
        int x = bb & 7, y = bb >> 3;
        gemm_body(hh, hl, wkvh, wkvl, kvp, nullptr,
                  HID, DKV2, NTOK, y * 128, x * 128, 0, smc);
    }
}

// o-proj (routed)
__global__ void __launch_bounds__(256, 2) gemm_o(
    const bf16* __restrict__ oh, const bf16* __restrict__ ol,
    const bf16* __restrict__ woh, const bf16* __restrict__ wol,
    float* __restrict__ out, const int* __restrict__ sort_idx)
{
    extern __shared__ char smc[];
    int bid = blockIdx.x;
    int x = bid & 15, y = (bid >> 4) & 3, z = bid >> 6;
    gemm_body(oh, ol,
              woh + (size_t)z * DQ * HID, wol + (size_t)z * DQ * HID,
              out, sort_idx, DQ, HID, CHUNK, y * 128, x * 128, z * CHUNK, smc);
}

// ---------------------------------------------------------------------------
// Fused attention prep: q/k RMSNorm+RoPE splits + v split, one launch.
// ---------------------------------------------------------------------------
__device__ __forceinline__ void norm_rope_warp(
    const float* __restrict__ x, int instride, const float* __restrict__ w,
    const int* __restrict__ pos, int n_heads, float sc,
    bf16* __restrict__ Hi, bf16* __restrict__ Lo, int warp, int lane)
{
    int t = warp / n_heads;
    int h = warp - t * n_heads;
    const float* row = x + (size_t)t * instride + (size_t)h * HD;
    float x1 = row[lane];
    float x2 = row[lane + 32];
    float ss = x1 * x1 + x2 * x2;
#pragma unroll
    for (int o = 16; o; o >>= 1) ss += __shfl_xor_sync(0xffffffff, ss, o);
    float r = rsqrtf(ss * (1.0f / 64.0f) + 1e-6f);
    float y1 = x1 * r * w[lane];
    float y2 = x2 * r * w[lane + 32];
    float p = (float)pos[t];
    float inv = powf(10000.0f, -(float)lane * (1.0f / 32.0f));
    float fr = p * inv;
    float s, c;
    sincosf(fr, &s, &c);
    float o1 = (y1 * c - y2 * s) * sc;
    float o2 = (y2 * c + y1 * s) * sc;
    size_t base = (size_t)t * (n_heads * HD) + (size_t)h * HD;
    bf16 h1, l1, h2, l2;
    bf_split(o1, h1, l1);
    bf_split(o2, h2, l2);
    Hi[base + lane] = h1;      Lo[base + lane] = l1;
    Hi[base + lane + 32] = h2; Lo[base + lane + 32] = l2;
}

__global__ void __launch_bounds__(256) prep_attn(
    const float* __restrict__ qp, const float* __restrict__ kvp,
    const float* __restrict__ q_norm_w, const float* __restrict__ k_norm_w,
    const int* __restrict__ pos,
    bf16* __restrict__ qh, bf16* __restrict__ ql,
    bf16* __restrict__ kh2, bf16* __restrict__ kl2,
    bf16* __restrict__ vh, bf16* __restrict__ vl)
{
    int b = blockIdx.x;
    int tid = threadIdx.x;
    int lane = tid & 31;
    if (b < 8192) {           // q norm+rope: NTOK*NH warps
        int warp = b * 8 + (tid >> 5);
        norm_rope_warp(qp, DQ, q_norm_w, pos, NH, 0.125f, qh, ql, warp, lane);
    } else if (b < 10240) {   // k norm+rope: NTOK*NKV warps
        int warp = (b - 8192) * 8 + (tid >> 5);
        norm_rope_warp(kvp, DKV2, k_norm_w, pos, NKV, 1.0f, kh2, kl2, warp, lane);
    } else {                  // v split from kv columns [512,1024)
        int i = (b - 10240) * 256 + tid;
        int r = i / (DKV / 4);
        int c = i % (DKV / 4);
        float4 v = *reinterpret_cast<const float4*>(kvp + (size_t)r * DKV2 + DKV + c * 4);
        bf16 h[4], l[4];
        bf_split(v.x, h[0], l[0]); bf_split(v.y, h[1], l[1]);
        bf_split(v.z, h[2], l[2]); bf_split(v.w, h[3], l[3]);
        *reinterpret_cast<uint2*>(vh + (size_t)r * DKV + c * 4) = *reinterpret_cast<uint2*>(h);
        *reinterpret_cast<uint2*>(vl + (size_t)r * DKV + c * 4) = *reinterpret_cast<uint2*>(l);
    }
}

// ---------------------------------------------------------------------------
// Tensor-core flash attention, AQ=64 / 128 threads -> 2 CTAs/SM.
// ---------------------------------------------------------------------------
#define AQ 64
#define AK 64
#define LDK 72
#define QSM (AQ * LDK)     // 4608
#define KSM (AK * LDK)     // 4608
#define ASMEM ((2 * QSM + 8 * KSM) * 2 + 2 * AK * 4)   // 92672

__device__ __forceinline__ void attn_issue(
    uint32_t sbase, int s, int kt, int kvh, int tid,
    const bf16* __restrict__ kh_g, const bf16* __restrict__ kl_g,
    const bf16* __restrict__ vh_g, const bf16* __restrict__ vl_g,
    const int* __restrict__ pos, int* __restrict__ kpos_sm)
{
#pragma unroll
    for (int i = 0; i < 16; i++) {
        int f = tid + i * 128;          // 0..2047
        int arr = f >> 9;
        int r = (f >> 3) & 63;
        int seg = f & 7;
        const bf16* src = (arr == 0) ? kh_g : (arr == 1) ? kl_g
                        : (arr == 2) ? vh_g : vl_g;
        uint32_t dst = sbase + (uint32_t)(2 * QSM + (s * 4 + arr) * KSM + r * LDK) * 2
                     + seg * 16;
        CP16(dst, src + (size_t)(kt * AK + r) * DKV + (size_t)kvh * HD + seg * 8);
    }
    if (tid < AK) kpos_sm[s * AK + tid] = pos[kt * AK + tid];
    CP_COMMIT();
}

__global__ void __launch_bounds__(128, 2) attn_mma(
    const bf16* __restrict__ qh_g, const bf16* __restrict__ ql_g,
    const bf16* __restrict__ kh_g, const bf16* __restrict__ kl_g,
    const bf16* __restrict__ vh_g, const bf16* __restrict__ vl_g,
    const int* __restrict__ pos,
    bf16* __restrict__ oh_g, bf16* __restrict__ ol_g)
{
    extern __shared__ char sm[];
    const uint32_t sbase = smem_u32(sm);
    int* kpos = (int*)(sm + (size_t)(2 * QSM + 8 * KSM) * 2);

    const int tid = threadIdx.x;
    const int w = tid >> 5;
    const int l = tid & 31;
    const int qt = gridDim.x - 1 - blockIdx.x;   // heavy tiles first
    const int h = blockIdx.y;
    const int kvh = h >> 2;
    const int q0 = qt * AQ;
    const int ntile = qt + 1;

    attn_issue(sbase, 0, 0, kvh, tid, kh_g, kl_g, vh_g, vl_g, pos, kpos);
    attn_issue(sbase, 1, 1 < ntile ? 1 : 0, kvh, tid, kh_g, kl_g, vh_g, vl_g, pos, kpos);

    // stage Q (hi, lo): 64 rows x 8 segs x 2 arrays = 1024 16B lines
#pragma unroll
    for (int i = 0; i < 8; i++) {
        int f = tid + i * 128;
        int arr = f >> 9;
        int r = (f >> 3) & 63;
        int seg = f & 7;
        const bf16* src = arr ? ql_g : qh_g;
        uint4 v = *reinterpret_cast<const uint4*>(
            src + (size_t)(q0 + r) * DQ + (size_t)h * HD + seg * 8);
        *reinterpret_cast<uint4*>(sm + (size_t)(arr * QSM + r * LDK) * 2 + seg * 16) = v;
    }
    __syncthreads();

    const int rq = l >> 2;
    const int cq = l & 3;
    const int row0 = w * 16 + rq;

    const uint32_t* smw = (const uint32_t*)sm;
    uint32_t qfh[4][4], qfl[4][4];
#pragma unroll
    for (int kf = 0; kf < 4; kf++) {
        int b = kf * 8 + cq;
        qfh[kf][0] = smw[row0 * 36 + b];
        qfh[kf][1] = smw[(row0 + 8) * 36 + b];
        qfh[kf][2] = smw[row0 * 36 + b + 4];
        qfh[kf][3] = smw[(row0 + 8) * 36 + b + 4];
        qfl[kf][0] = smw[(QSM / 2) + row0 * 36 + b];
        qfl[kf][1] = smw[(QSM / 2) + (row0 + 8) * 36 + b];
        qfl[kf][2] = smw[(QSM / 2) + row0 * 36 + b + 4];
        qfl[kf][3] = smw[(QSM / 2) + (row0 + 8) * 36 + b + 4];
    }
    const int qp0 = pos[q0 + row0];
    const int qp1 = pos[q0 + row0 + 8];

    float o[8][4];
#pragma unroll
    for (int nf = 0; nf < 8; nf++)
#pragma unroll
        for (int e = 0; e < 4; e++) o[nf][e] = 0.f;
    float m0 = -1e30f, m1 = -1e30f, l0 = 0.f, l1 = 0.f;

    const int lrow16 = l & 15;
    const int lsel = l >> 4;
    const uint32_t lnK = (((l >> 4) * 8 + (l & 7)) * LDK + ((l >> 3) & 1) * 8) * 2;

    for (int kt = 0; kt < ntile; kt++) {
        if (kt + 1 < ntile) asm volatile("cp.async.wait_group 1;" ::: "memory");
        else                asm volatile("cp.async.wait_group 0;" ::: "memory");
        __syncthreads();

        const int s = kt & 1;
        const uint32_t khb = sbase + (uint32_t)(2 * QSM + (s * 4 + 0) * KSM) * 2;
        const uint32_t vhb = sbase + (uint32_t)(2 * QSM + (s * 4 + 2) * KSM) * 2;
        const uint32_t vlb = sbase + (uint32_t)(2 * QSM + (s * 4 + 3) * KSM) * 2;

        float sv[8][4];
#pragma unroll
        for (int nf = 0; nf < 8; nf++)
#pragma unroll
            for (int e = 0; e < 4; e++) sv[nf][e] = 0.f;

#pragma unroll
        for (int kf = 0; kf < 4; kf++) {
#pragma unroll
            for (int np = 0; np < 4; np++) {
                uint32_t koff = khb + (uint32_t)(np * 16 * LDK) * 2 + kf * 32 + lnK;
                uint32_t b0, b1, b2, b3, c0, c1, c2, c3;
                LDSM_4(b0, b1, b2, b3, koff);
                LDSM_4(c0, c1, c2, c3, koff + KSM * 2);
                MMA16816(sv[2 * np], qfh[kf], b0, b1);
                MMA16816(sv[2 * np], qfh[kf], c0, c1);
                MMA16816(sv[2 * np], qfl[kf], b0, b1);
                MMA16816(sv[2 * np + 1], qfh[kf], b2, b3);
                MMA16816(sv[2 * np + 1], qfh[kf], c2, c3);
                MMA16816(sv[2 * np + 1], qfl[kf], b2, b3);
            }
        }

        if (kt == qt) {       // only the diagonal tile crosses the mask
            const int* kp = kpos + s * AK;
#pragma unroll
            for (int nf = 0; nf < 8; nf++) {
                int c = nf * 8 + cq * 2;
                int k0 = kp[c], k1 = kp[c + 1];
                if (k0 > qp0) sv[nf][0] = -1e30f;
                if (k1 > qp0) sv[nf][1] = -1e30f;
                if (k0 > qp1) sv[nf][2] = -1e30f;
                if (k1 > qp1) sv[nf][3] = -1e30f;
            }
        }

        float mt0 = -1e30f, mt1 = -1e30f;
#pragma unroll
        for (int nf = 0; nf < 8; nf++) {
            mt0 = fmaxf(mt0, fmaxf(sv[nf][0], sv[nf][1]));
            mt1 = fmaxf(mt1, fmaxf(sv[nf][2], sv[nf][3]));
        }
        mt0 = fmaxf(mt0, __shfl_xor_sync(0xffffffff, mt0, 1));
        mt0 = fmaxf(mt0, __shfl_xor_sync(0xffffffff, mt0, 2));
        mt1 = fmaxf(mt1, __shfl_xor_sync(0xffffffff, mt1, 1));
        mt1 = fmaxf(mt1, __shfl_xor_sync(0xffffffff, mt1, 2));
        float mn0 = fmaxf(m0, mt0), mn1 = fmaxf(m1, mt1);
        float a0 = __expf(m0 - mn0), a1 = __expf(m1 - mn1);
        m0 = mn0; m1 = mn1;
#pragma unroll
        for (int nf = 0; nf < 8; nf++) {
            o[nf][0] *= a0; o[nf][1] *= a0;
            o[nf][2] *= a1; o[nf][3] *= a1;
        }
        float rs0 = 0.f, rs1 = 0.f;
#pragma unroll
        for (int nf = 0; nf < 8; nf++) {
            sv[nf][0] = __expf(sv[nf][0] - mn0); rs0 += sv[nf][0];
            sv[nf][1] = __expf(sv[nf][1] - mn0); rs0 += sv[nf][1];
            sv[nf][2] = __expf(sv[nf][2] - mn1); rs1 += sv[nf][2];
            sv[nf][3] = __expf(sv[nf][3] - mn1); rs1 += sv[nf][3];
        }
        rs0 += __shfl_xor_sync(0xffffffff, rs0, 1);
        rs0 += __shfl_xor_sync(0xffffffff, rs0, 2);
        rs1 += __shfl_xor_sync(0xffffffff, rs1, 1);
        rs1 += __shfl_xor_sync(0xffffffff, rs1, 2);
        l0 = l0 * a0 + rs0;
        l1 = l1 * a1 + rs1;

#pragma unroll
        for (int kfk = 0; kfk < 4; kfk++) {
            uint32_t pah[4], pal[4];
            splitpack2(sv[2 * kfk][0], sv[2 * kfk][1], pah[0], pal[0]);
            splitpack2(sv[2 * kfk][2], sv[2 * kfk][3], pah[1], pal[1]);
            splitpack2(sv[2 * kfk + 1][0], sv[2 * kfk + 1][1], pah[2], pal[2]);
            splitpack2(sv[2 * kfk + 1][2], sv[2 * kfk + 1][3], pah[3], pal[3]);

            uint32_t vfh[8][2], vfl[8][2];
#pragma unroll
            for (int nfp = 0; nfp < 4; nfp++) {
                uint32_t off = (uint32_t)((kfk * 16 + lrow16) * LDK
                                          + nfp * 16 + lsel * 8) * 2;
                uint32_t r0, r1, r2, r3;
                LDSM_T4(r0, r1, r2, r3, vhb + off);
                vfh[2 * nfp][0] = r0;     vfh[2 * nfp][1] = r1;
                vfh[2 * nfp + 1][0] = r2; vfh[2 * nfp + 1][1] = r3;
                LDSM_T4(r0, r1, r2, r3, vlb + off);
                vfl[2 * nfp][0] = r0;     vfl[2 * nfp][1] = r1;
                vfl[2 * nfp + 1][0] = r2; vfl[2 * nfp + 1][1] = r3;
            }
#pragma unroll
            for (int nf = 0; nf < 8; nf++) {
                MMA16816(o[nf], pah, vfh[nf][0], vfh[nf][1]);
                MMA16816(o[nf], pah, vfl[nf][0], vfl[nf][1]);
                MMA16816(o[nf], pal, vfh[nf][0], vfh[nf][1]);
            }
        }

        __syncthreads();
        if (kt + 2 < ntile)
            attn_issue(sbase, s, kt + 2, kvh, tid, kh_g, kl_g, vh_g, vl_g, pos, kpos);
    }

    float i0 = 1.f / l0, i1 = 1.f / l1;
    int g0 = q0 + w * 16 + rq;
    int g1 = g0 + 8;
#pragma unroll
    for (int nf = 0; nf < 8; nf++) {
        int col = h * HD + nf * 8 + cq * 2;
        uint32_t ph, pl;
        splitpack2(o[nf][0] * i0, o[nf][1] * i0, ph, pl);
        *reinterpret_cast<uint32_t*>(oh_g + (size_t)g0 * DQ + col) = ph;
        *reinterpret_cast<uint32_t*>(ol_g + (size_t)g0 * DQ + col) = pl;
        splitpack2(o[nf][2] * i1, o[nf][3] * i1, ph, pl);
        *reinterpret_cast<uint32_t*>(oh_g + (size_t)g1 * DQ + col) = ph;
        *reinterpret_cast<uint32_t*>(ol_g + (size_t)g1 * DQ + col) = pl;
    }
}

// ---------------------------------------------------------------------------
extern "C" void kernel_launch(void* const* d_in, const int* in_sizes, int n_in,
                              void* d_out, int out_size)
{
    const float* hidden    = (const float*)d_in[0];
    const int*   positions = (const int*)  d_in[1];
    const int*   sort_idx  = (const int*)  d_in[2];
    const float* q_proj_w  = (const float*)d_in[3];
    const float* o_proj_w  = (const float*)d_in[4];
    const float* k_w       = (const float*)d_in[5];
    const float* v_w       = (const float*)d_in[6];
    const float* q_norm_w  = (const float*)d_in[7];
    const float* k_norm_w  = (const float*)d_in[8];
    float* out = (float*)d_out;

    float *qp, *kvp;
    bf16 *hh, *hl, *oh, *ol, *qh, *ql, *kh2, *kl2, *vh, *vl;
    bf16 *wqh, *wql, *woh, *wol, *wkvh, *wkvl;
    cudaGetSymbolAddress((void**)&qp, g_q);
    cudaGetSymbolAddress((void**)&kvp, g_kv);
    cudaGetSymbolAddress((void**)&hh, g_hh);
    cudaGetSymbolAddress((void**)&hl, g_hl);
    cudaGetSymbolAddress((void**)&oh, g_oh);
    cudaGetSymbolAddress((void**)&ol, g_ol);
    cudaGetSymbolAddress((void**)&qh, g_qh);
    cudaGetSymbolAddress((void**)&ql, g_ql);
    cudaGetSymbolAddress((void**)&kh2, g_kh2);
    cudaGetSymbolAddress((void**)&kl2, g_kl2);
    cudaGetSymbolAddress((void**)&vh, g_vh);
    cudaGetSymbolAddress((void**)&vl, g_vl);
    cudaGetSymbolAddress((void**)&wqh, g_wq_h);
    cudaGetSymbolAddress((void**)&wql, g_wq_l);
    cudaGetSymbolAddress((void**)&woh, g_wo_h);
    cudaGetSymbolAddress((void**)&wol, g_wo_l);
    cudaGetSymbolAddress((void**)&wkvh, g_wkv_h);
    cudaGetSymbolAddress((void**)&wkvl, g_wkv_l);

    cudaFuncSetAttribute(gemm_qkv, cudaFuncAttributeMaxDynamicSharedMemorySize, GEMM_SMEM);
    cudaFuncSetAttribute(gemm_o, cudaFuncAttributeMaxDynamicSharedMemorySize, GEMM_SMEM);
    cudaFuncSetAttribute(attn_mma, cudaFuncAttributeMaxDynamicSharedMemorySize, ASMEM);

    // 1) all weight transposes + hidden split
    prep_inputs<<<34816 + 4096, 256>>>(
        q_proj_w, o_proj_w, k_w, v_w, hidden,
        wqh, wql, woh, wol, wkvh, wkvl, hh, hl);

    // 2) q-proj (routed) + kv-proj, one launch
    gemm_qkv<<<384, 256, GEMM_SMEM>>>(hh, hl, wqh, wql, wkvh, wkvl, qp, kvp, sort_idx);

    // 3) RMSNorm+RoPE splits + v split, one launch
    prep_attn<<<10240 + 1024, 256>>>(qp, kvp, q_norm_w, k_norm_w, positions,
                                     qh, ql, kh2, kl2, vh, vl);

    // 4) flash attention (2 CTAs/SM)
    attn_mma<<<dim3(NTOK / AQ, NH), 128, ASMEM>>>(
        qh, ql, kh2, kl2, vh, vl, positions, oh, ol);

    // 5) o-proj (routed)
    gemm_o<<<256, 256, GEMM_SMEM>>>(oh, ol, woh, wol, out, sort_idx);
}